// round 12
// baseline (speedup 1.0000x reference)
#include <cuda_runtime.h>
#include <cuda_bf16.h>
#include <math.h>
#include <stdint.h>

#define NN 50000
#define EE 400000
#define GG 64
#define HC 256

// ---------------- scratch (static device globals) ---------------------------
__device__ float    g_h    [NN * HC];      // GEMM output (gather source), fp32
__device__ uint16_t g_xhi  [NN * 128];     // split of x (layer-1 A)
__device__ uint16_t g_xlo  [NN * 128];
__device__ uint16_t g_fhi  [NN * HC];      // split of feat (layers 2,3, fc1 A)
__device__ uint16_t g_flo  [NN * HC];
__device__ uint16_t g_bthi [5 * 256 * 256];// split transposed weights
__device__ uint16_t g_btlo [5 * 256 * 256];
__device__ float    g_as   [NN * 8];
__device__ float    g_ad   [NN * 8];
__device__ float    g_VeAll[96];
__device__ float    g_pool2[GG * 256];
// CSR
__device__ int   g_deg [NN];
__device__ int   g_rs  [NN];
__device__ int   g_wp  [NN];
__device__ int   g_part[128];
__device__ int   g_csrc[EE];
__device__ float g_cea [EE * 5];

// ---------------- helpers ---------------------------------------------------
__device__ __forceinline__ float elu1(float x) { return x > 0.0f ? x : expm1f(x); }
__device__ __forceinline__ float gelu1(float x) {
    return 0.5f * x * (1.0f + erff(x * 0.70710678118654752f));
}
__device__ __forceinline__ uint16_t bf16of(float x) {
    uint16_t b;
    asm("cvt.rn.bf16.f32 %0, %1;" : "=h"(b) : "f"(x));
    return b;
}
__device__ __forceinline__ float f32of(uint16_t b) {
    float r;
    asm("cvt.f32.bf16 %0, %1;" : "=f"(r) : "h"(b));
    return r;
}
__device__ __forceinline__ void split2(float v, uint16_t& hi, uint16_t& lo) {
    hi = bf16of(v);
    lo = bf16of(v - f32of(hi));
}

__device__ __forceinline__ void mma_bf16(float* d, const uint32_t* a,
                                         uint32_t b0, uint32_t b1) {
    asm volatile(
        "mma.sync.aligned.m16n8k16.row.col.f32.bf16.bf16.f32 "
        "{%0,%1,%2,%3}, {%4,%5,%6,%7}, {%8,%9}, {%0,%1,%2,%3};"
        : "+f"(d[0]), "+f"(d[1]), "+f"(d[2]), "+f"(d[3])
        : "r"(a[0]), "r"(a[1]), "r"(a[2]), "r"(a[3]), "r"(b0), "r"(b1));
}

#define LDSM4(r, addr) \
    asm volatile("ldmatrix.sync.aligned.m8n8.x4.shared.b16 {%0,%1,%2,%3}, [%4];" \
        : "=r"((r)[0]), "=r"((r)[1]), "=r"((r)[2]), "=r"((r)[3]) : "r"(addr))

// ---------------- warp-MMA 3xBF16 GEMM, 128x128 CTA tile ---------------------
// All operands PRE-SPLIT bf16 hi/lo. Zero conversion work in the main loop.
#define S32 12
#define TILE32 (128 * S32)
#define BUF32 (4 * TILE32)

__global__ void __launch_bounds__(256, 2)
mma_gemm_k(const uint16_t* __restrict__ Ahi, const uint16_t* __restrict__ Alo,
           const uint16_t* __restrict__ Bhi, const uint16_t* __restrict__ Blo,
           float* __restrict__ C, int Nrows, int K, int ncols,
           const float* __restrict__ bias, int act,
           const float* __restrict__ att_s, const float* __restrict__ att_d,
           float* __restrict__ as_out, float* __restrict__ ad_out,
           float* __restrict__ pool_out, const int* __restrict__ batchv)
{
    extern __shared__ uint32_t sm32[];
    uint32_t sbase;
    asm("{ .reg .u64 t; cvta.to.shared.u64 t, %1; cvt.u32.u64 %0, t; }"
        : "=r"(sbase) : "l"(sm32));

    const int tid = threadIdx.x;
    const int lane = tid & 31, wid = tid >> 5;
    const int wr = wid >> 2, wc = wid & 3;
    const int tg = lane >> 2, tig = lane & 3;
    const int m0 = blockIdx.x * 128, n0 = blockIdx.y * 128;
    const int jcnt = max(0, min(4, (ncols - n0 - wc * 32 + 7) >> 3));

    const int lr = lane & 7, seg = lane >> 3;
    const uint32_t aoff = (uint32_t)((wr * 64 + lr + (seg & 1) * 8) * S32) * 4
                        + (uint32_t)(seg >> 1) * 16;
    const uint32_t boff = (uint32_t)((wc * 32 + (seg >> 1) * 8 + lr) * S32) * 4
                        + (uint32_t)(seg & 1) * 16;

    float acc[4][4][4];
    #pragma unroll
    for (int i = 0; i < 4; i++)
        #pragma unroll
        for (int j = 0; j < 4; j++)
            #pragma unroll
            for (int q = 0; q < 4; q++) acc[i][j][q] = 0.0f;

    const int nc = K / 16;
    // per-chunk staging: one uint4 (8 bf16) per thread per tile
    const int lrow = tid >> 1, lq = tid & 1;
    uint4 sAh, sAl, sBh, sBl;

    auto loadG = [&](int c) {
        const int k0 = c * 16;
        const uint4 z = make_uint4(0, 0, 0, 0);
        int grow = m0 + lrow;
        size_t ao = (size_t)grow * K + k0 + lq * 8;
        sAh = (grow < Nrows) ? *(const uint4*)&Ahi[ao] : z;
        sAl = (grow < Nrows) ? *(const uint4*)&Alo[ao] : z;
        int gn = n0 + lrow;
        size_t bo = (size_t)gn * K + k0 + lq * 8;
        sBh = (gn < ncols) ? *(const uint4*)&Bhi[bo] : z;
        sBl = (gn < ncols) ? *(const uint4*)&Blo[bo] : z;
    };
    auto storeS = [&](int buf) {
        uint32_t* base = sm32 + buf * BUF32;
        int o = lrow * S32 + lq * 4;
        *(uint4*)(base + o)              = sAh;
        *(uint4*)(base + TILE32 + o)     = sAl;
        *(uint4*)(base + 2 * TILE32 + o) = sBh;
        *(uint4*)(base + 3 * TILE32 + o) = sBl;
    };
    auto compute = [&](int buf) {
        const uint32_t bb = sbase + (uint32_t)buf * BUF32 * 4;
        const uint32_t a_h = bb + aoff;
        const uint32_t a_l = a_h + TILE32 * 4;
        const uint32_t b_h = bb + 2 * TILE32 * 4 + boff;
        const uint32_t b_l = b_h + TILE32 * 4;

        uint32_t ah[4][4], al[4][4], bh[4][2], bl[4][2];
        #pragma unroll
        for (int i = 0; i < 4; i++) {
            LDSM4(ah[i], a_h + (uint32_t)(i * 16 * S32) * 4);
            LDSM4(al[i], a_l + (uint32_t)(i * 16 * S32) * 4);
        }
        #pragma unroll
        for (int jp = 0; jp < 2; jp++) {
            uint32_t t[4];
            LDSM4(t, b_h + (uint32_t)(jp * 16 * S32) * 4);
            bh[jp * 2][0] = t[0]; bh[jp * 2][1] = t[1];
            bh[jp * 2 + 1][0] = t[2]; bh[jp * 2 + 1][1] = t[3];
            LDSM4(t, b_l + (uint32_t)(jp * 16 * S32) * 4);
            bl[jp * 2][0] = t[0]; bl[jp * 2][1] = t[1];
            bl[jp * 2 + 1][0] = t[2]; bl[jp * 2 + 1][1] = t[3];
        }
        #pragma unroll
        for (int j = 0; j < 4; j++) {
            if (j >= jcnt) break;
            #pragma unroll
            for (int i = 0; i < 4; i++) {
                mma_bf16(acc[i][j], ah[i], bh[j][0], bh[j][1]);
                mma_bf16(acc[i][j], ah[i], bl[j][0], bl[j][1]);
                mma_bf16(acc[i][j], al[i], bh[j][0], bh[j][1]);
            }
        }
    };

    loadG(0); storeS(0);
    __syncthreads();
    for (int c = 0; c < nc; c++) {
        if (c + 1 < nc) loadG(c + 1);
        compute(c & 1);
        if (c + 1 < nc) storeS((c + 1) & 1);
        __syncthreads();
    }

    // ---- C store epilogue ----
    if (C) {
        #pragma unroll
        for (int i = 0; i < 4; i++) {
            int row = m0 + wr * 64 + i * 16 + tg;
            #pragma unroll
            for (int j = 0; j < 4; j++) {
                int col = n0 + wc * 32 + j * 8 + tig * 2;
                if (col >= ncols) continue;
                #pragma unroll
                for (int half = 0; half < 2; half++) {
                    int r = row + half * 8;
                    if (r >= Nrows) continue;
                    float v0 = acc[i][j][half * 2 + 0];
                    float v1 = acc[i][j][half * 2 + 1];
                    if (bias) { v0 += bias[col]; v1 += bias[col + 1]; }
                    if (act == 1) { v0 = gelu1(v0); v1 = gelu1(v1); }
                    *(float2*)&C[(size_t)r * ncols + col] = make_float2(v0, v1);
                }
            }
        }
    }

    // ---- fused node-attention dots (plain stores, 8-slot layout) ----
    if (as_out) {
        const int slot = (n0 >> 5) + wc;
        #pragma unroll
        for (int i = 0; i < 4; i++) {
            float s1 = 0.f, d1 = 0.f, s2 = 0.f, d2 = 0.f;
            #pragma unroll
            for (int j = 0; j < 4; j++) {
                int col = n0 + wc * 32 + j * 8 + tig * 2;
                float a0 = att_s[col], a1 = att_s[col + 1];
                float b0 = att_d[col], b1 = att_d[col + 1];
                s1 += acc[i][j][0] * a0 + acc[i][j][1] * a1;
                d1 += acc[i][j][0] * b0 + acc[i][j][1] * b1;
                s2 += acc[i][j][2] * a0 + acc[i][j][3] * a1;
                d2 += acc[i][j][2] * b0 + acc[i][j][3] * b1;
            }
            s1 += __shfl_xor_sync(0xffffffffu, s1, 1); s1 += __shfl_xor_sync(0xffffffffu, s1, 2);
            d1 += __shfl_xor_sync(0xffffffffu, d1, 1); d1 += __shfl_xor_sync(0xffffffffu, d1, 2);
            s2 += __shfl_xor_sync(0xffffffffu, s2, 1); s2 += __shfl_xor_sync(0xffffffffu, s2, 2);
            d2 += __shfl_xor_sync(0xffffffffu, d2, 1); d2 += __shfl_xor_sync(0xffffffffu, d2, 2);
            if (tig == 0) {
                int r1 = m0 + wr * 64 + i * 16 + tg;
                int r2 = r1 + 8;
                if (r1 < Nrows) { as_out[r1 * 8 + slot] = s1; ad_out[r1 * 8 + slot] = d1; }
                if (r2 < Nrows) { as_out[r2 * 8 + slot] = s2; ad_out[r2 * 8 + slot] = d2; }
            }
        }
    }

    // ---- fused gelu + segment-sum pooling (fc1 + pool) ----
    if (pool_out) {
        const int rbase = m0 + wr * 64;
        bool uniform = (rbase + 63 < Nrows) && (batchv[rbase] == batchv[rbase + 63]);
        if (uniform) {
            int g = batchv[rbase];
            #pragma unroll
            for (int j = 0; j < 4; j++) {
                #pragma unroll
                for (int qc = 0; qc < 2; qc++) {
                    int col = n0 + wc * 32 + j * 8 + tig * 2 + qc;
                    float sum = 0.f;
                    #pragma unroll
                    for (int i = 0; i < 4; i++)
                        #pragma unroll
                        for (int half = 0; half < 2; half++)
                            sum += gelu1(acc[i][j][half * 2 + qc] + bias[col]);
                    atomicAdd(&pool_out[g * 256 + col], sum);
                }
            }
        } else {
            #pragma unroll
            for (int i = 0; i < 4; i++)
                #pragma unroll
                for (int j = 0; j < 4; j++)
                    #pragma unroll
                    for (int q = 0; q < 4; q++) {
                        int r = rbase + i * 16 + tg + (q >> 1) * 8;
                        if (r >= Nrows) continue;
                        int col = n0 + wc * 32 + j * 8 + tig * 2 + (q & 1);
                        float v = gelu1(acc[i][j][q] + bias[col]);
                        atomicAdd(&pool_out[batchv[r] * 256 + col], v);
                    }
        }
    }
}

// ---------------- batched weight transpose + split (all 5 at once) ----------
__global__ void transpose_all_k(const float* __restrict__ W1, const float* __restrict__ W2,
                                const float* __restrict__ W3, const float* __restrict__ f1,
                                const float* __restrict__ f2)
{
    __shared__ float t[32][33];
    int z = blockIdx.z;
    const float* W = (z == 0) ? W1 : (z == 1) ? W2 : (z == 2) ? W3 : (z == 3) ? f1 : f2;
    int K = (z == 0) ? 128 : 256;
    int M = (z == 4) ? 32 : 256;
    uint16_t* Bh = g_bthi + z * 65536;
    uint16_t* Bl = g_btlo + z * 65536;
    int m0 = blockIdx.x * 32, k0 = blockIdx.y * 32;
    if (m0 >= M || k0 >= K) return;
    for (int i = threadIdx.y; i < 32; i += 8) {
        int k = k0 + i, m = m0 + threadIdx.x;
        t[i][threadIdx.x] = (k < K && m < M) ? W[(size_t)k * M + m] : 0.f;
    }
    __syncthreads();
    for (int i = threadIdx.y; i < 32; i += 8) {
        int m = m0 + i, k = k0 + threadIdx.x;
        if (m < M && k < K) {
            uint16_t hi, lo;
            split2(t[threadIdx.x][i], hi, lo);
            Bh[(size_t)m * K + k] = hi;
            Bl[(size_t)m * K + k] = lo;
        }
    }
}

// ---------------- x split (once) ----------------------------------------------
__global__ void xsplit_k(const float* __restrict__ x)
{
    int i = blockIdx.x * blockDim.x + threadIdx.x;
    if (i >= NN * 32) return;   // float4 granularity over NN*128
    float4 v = ((const float4*)x)[i];
    uint16_t h0, l0, h1, l1, h2, l2, h3, l3;
    split2(v.x, h0, l0); split2(v.y, h1, l1);
    split2(v.z, h2, l2); split2(v.w, h3, l3);
    ((ushort4*)g_xhi)[i] = make_ushort4(h0, h1, h2, h3);
    ((ushort4*)g_xlo)[i] = make_ushort4(l0, l1, l2, l3);
}

// ---------------- batched Ve ---------------------------------------------------
__global__ void ve_all_k(const float* __restrict__ We1, const float* __restrict__ ae1,
                         const float* __restrict__ We2, const float* __restrict__ ae2,
                         const float* __restrict__ We3, const float* __restrict__ ae3)
{
    int tid = threadIdx.x;
    const float* We; const float* ae; int H, base, loc;
    if (tid < 40)      { We = We1; ae = ae1; H = 8; base = 0;  loc = tid; }
    else if (tid < 80) { We = We2; ae = ae2; H = 8; base = 40; loc = tid - 40; }
    else if (tid < 85) { We = We3; ae = ae3; H = 1; base = 80; loc = tid - 80; }
    else return;
    int d = loc / H, h = loc % H;
    int C = 256 / H;
    float s = 0.0f;
    for (int c = 0; c < C; c++) s += We[d * 256 + h * C + c] * ae[h * C + c];
    g_VeAll[base + loc] = s;
}

// ---------------- init ----------------------------------------------------------
__global__ void init_k()
{
    int i = blockIdx.x * blockDim.x + threadIdx.x;
    if (i < NN) g_deg[i] = 0;
    if (i < GG * 256) g_pool2[i] = 0.0f;
}

// ---------------- CSR build ------------------------------------------------------
__global__ void hist_k(const int* __restrict__ dst)
{
    int e = blockIdx.x * blockDim.x + threadIdx.x;
    if (e < EE) atomicAdd(&g_deg[dst[e]], 1);
}
__global__ void scan1_k()
{
    __shared__ int s[512];
    int tid = threadIdx.x;
    int i = blockIdx.x * 512 + tid;
    int v = (i < NN) ? g_deg[i] : 0;
    s[tid] = v;
    __syncthreads();
    for (int off = 1; off < 512; off <<= 1) {
        int t = (tid >= off) ? s[tid - off] : 0;
        __syncthreads();
        s[tid] += t;
        __syncthreads();
    }
    if (i < NN) g_rs[i] = s[tid] - v;
    if (tid == 511) g_part[blockIdx.x] = s[511];
}
__global__ void scan2_k(int nb)
{
    __shared__ int s[128];
    int tid = threadIdx.x;
    int v = (tid < nb) ? g_part[tid] : 0;
    s[tid] = v;
    __syncthreads();
    for (int off = 1; off < 128; off <<= 1) {
        int t = (tid >= off) ? s[tid - off] : 0;
        __syncthreads();
        s[tid] += t;
        __syncthreads();
    }
    if (tid < nb) g_part[tid] = s[tid] - v;
}
__global__ void scan3_k()
{
    int i = blockIdx.x * blockDim.x + threadIdx.x;
    if (i >= NN) return;
    int r = g_rs[i] + g_part[i >> 9];
    g_rs[i] = r;
    g_wp[i] = r;
}
__global__ void scatter_k(const int* __restrict__ src, const int* __restrict__ dst,
                          const float* __restrict__ ea)
{
    int e = blockIdx.x * blockDim.x + threadIdx.x;
    if (e >= EE) return;
    int d = dst[e];
    int pos = atomicAdd(&g_wp[d], 1);
    g_csrc[pos] = src[e];
    #pragma unroll
    for (int i = 0; i < 5; i++) g_cea[(size_t)pos * 5 + i] = ea[(size_t)e * 5 + i];
}

// ---------------- fused single-pass edge softmax + aggregation ---------------
// Output written as PRE-SPLIT bf16 hi/lo (consumed as GEMM A operand).
template <int H>
__global__ void __launch_bounds__(256)
gat_edge_k(const float* __restrict__ as_, const float* __restrict__ ad_,
           const float* __restrict__ hfeat, const float* __restrict__ bias,
           uint16_t* __restrict__ outhi, uint16_t* __restrict__ outlo, int veBase)
{
    int w = (blockIdx.x * blockDim.x + threadIdx.x) >> 5;
    if (w >= NN) return;
    int lane = threadIdx.x & 31;
    const int head = (H == 8) ? (lane >> 2) : 0;
    const int tig = lane & 3;
    const int col0 = lane * 8;

    float ve[5];
    #pragma unroll
    for (int i = 0; i < 5; i++) ve[i] = g_VeAll[veBase + i * H + head];

    float adv;
    if (H == 1) {
        float4 a0 = *(const float4*)&ad_[w * 8];
        float4 a1 = *(const float4*)&ad_[w * 8 + 4];
        adv = a0.x + a0.y + a0.z + a0.w + a1.x + a1.y + a1.z + a1.w;
    } else {
        adv = ad_[w * 8 + head];
    }
    const int r0 = g_rs[w], dg = g_deg[w];

    float den = 0.0f;
    float acc[8];
    #pragma unroll
    for (int q = 0; q < 8; q++) acc[q] = 0.0f;

    for (int j = 0; j < dg; j += 4) {
        int jj = j + tig;
        bool valid = jj < dg;
        int je = r0 + (valid ? jj : 0);
        int sq = g_csrc[je];
        const float* ce = g_cea + (size_t)je * 5;
        float asv;
        if (H == 1) {
            float4 a0 = *(const float4*)&as_[sq * 8];
            float4 a1 = *(const float4*)&as_[sq * 8 + 4];
            asv = a0.x + a0.y + a0.z + a0.w + a1.x + a1.y + a1.z + a1.w;
        } else {
            asv = as_[sq * 8 + head];
        }
        float a = asv + adv;
        #pragma unroll
        for (int i = 0; i < 5; i++) a = fmaf(ce[i], ve[i], a);
        a = a > 0.0f ? a : 0.2f * a;
        float pq = valid ? __expf(a) : 0.0f;
        #pragma unroll
        for (int q = 0; q < 4; q++) {
            float p = __shfl_sync(0xffffffffu, pq, (lane & ~3) | q);
            int s   = __shfl_sync(0xffffffffu, sq, q);
            if (p != 0.0f) {
                den += p;
                const float4* hp = (const float4*)(hfeat + (size_t)s * 256 + col0);
                float4 v0 = hp[0], v1 = hp[1];
                acc[0] = fmaf(p, v0.x, acc[0]); acc[1] = fmaf(p, v0.y, acc[1]);
                acc[2] = fmaf(p, v0.z, acc[2]); acc[3] = fmaf(p, v0.w, acc[3]);
                acc[4] = fmaf(p, v1.x, acc[4]); acc[5] = fmaf(p, v1.y, acc[5]);
                acc[6] = fmaf(p, v1.z, acc[6]); acc[7] = fmaf(p, v1.w, acc[7]);
            }
        }
    }

    float inv = 1.0f / (den + 1e-16f);
    uint16_t hi[8], lo[8];
    #pragma unroll
    for (int q = 0; q < 8; q++) {
        float v = elu1(acc[q] * inv + bias[col0 + q]);
        split2(v, hi[q], lo[q]);
    }
    *(ushort4*)&outhi[(size_t)w * 256 + col0]     = make_ushort4(hi[0], hi[1], hi[2], hi[3]);
    *(ushort4*)&outhi[(size_t)w * 256 + col0 + 4] = make_ushort4(hi[4], hi[5], hi[6], hi[7]);
    *(ushort4*)&outlo[(size_t)w * 256 + col0]     = make_ushort4(lo[0], lo[1], lo[2], lo[3]);
    *(ushort4*)&outlo[(size_t)w * 256 + col0 + 4] = make_ushort4(lo[4], lo[5], lo[6], lo[7]);
}

// ---------------- final: out[g] = (pool2[g]/cnt[g]) @ fc2^T + b ----------------
__global__ void pool_fin2_k(const int* __restrict__ batch,
                            const uint16_t* __restrict__ fc2thi,
                            const uint16_t* __restrict__ fc2tlo,
                            const float* __restrict__ fcb2,
                            float* __restrict__ out)
{
    __shared__ float v[256];
    __shared__ float sinv;
    int g = blockIdx.x, t = threadIdx.x;
    if (t == 0) {
        int a = 0, b = NN;
        while (a < b) { int m = (a + b) >> 1; if (batch[m] < g) a = m + 1; else b = m; }
        int lo = a;
        a = lo; b = NN;
        while (a < b) { int m = (a + b) >> 1; if (batch[m] < g + 1) a = m + 1; else b = m; }
        sinv = 1.0f / fmaxf((float)(a - lo), 1.0f);
    }
    __syncthreads();
    v[t] = g_pool2[g * 256 + t] * sinv;
    __syncthreads();
    if (t < 32) {
        float s = fcb2[t];
        const uint16_t* wh = fc2thi + t * 256;
        const uint16_t* wl = fc2tlo + t * 256;
        #pragma unroll 8
        for (int k = 0; k < 256; k++)
            s = fmaf(v[k], f32of(wh[k]) + f32of(wl[k]), s);
        out[g * 32 + t] = s;
    }
}

// ============================================================================
static void launch_gemm(const uint16_t* ahi, const uint16_t* alo,
                        const uint16_t* bhi, const uint16_t* blo, float* C,
                        int n, int K, int ncols, const float* bias, int act,
                        const float* att_s = nullptr, const float* att_d = nullptr,
                        float* as_o = nullptr, float* ad_o = nullptr,
                        float* pool_o = nullptr, const int* batchv = nullptr)
{
    dim3 grid((n + 127) / 128, (ncols + 127) / 128);
    mma_gemm_k<<<grid, 256, 2 * BUF32 * sizeof(uint32_t)>>>(
        ahi, alo, bhi, blo, C, n, K, ncols, bias, act,
        att_s, att_d, as_o, ad_o, pool_o, batchv);
}

extern "C" void kernel_launch(void* const* d_in, const int* in_sizes, int n_in,
                              void* d_out, int out_size)
{
    const float* x     = (const float*)d_in[0];
    const int*   ei    = (const int*)  d_in[1];
    const float* ea    = (const float*)d_in[2];
    const int*   batch = (const int*)  d_in[3];
    const float* W1  = (const float*)d_in[4];
    const float* as1 = (const float*)d_in[5];
    const float* ad1 = (const float*)d_in[6];
    const float* We1 = (const float*)d_in[7];
    const float* ae1 = (const float*)d_in[8];
    const float* b1  = (const float*)d_in[9];
    const float* W2  = (const float*)d_in[10];
    const float* as2 = (const float*)d_in[11];
    const float* ad2 = (const float*)d_in[12];
    const float* We2 = (const float*)d_in[13];
    const float* ae2 = (const float*)d_in[14];
    const float* b2  = (const float*)d_in[15];
    const float* W3  = (const float*)d_in[16];
    const float* as3 = (const float*)d_in[17];
    const float* ad3 = (const float*)d_in[18];
    const float* We3 = (const float*)d_in[19];
    const float* ae3 = (const float*)d_in[20];
    const float* b3  = (const float*)d_in[21];
    const float* fcW1 = (const float*)d_in[22];
    const float* fcb1 = (const float*)d_in[23];
    const float* fcW2 = (const float*)d_in[24];
    const float* fcb2 = (const float*)d_in[25];

    const int* src = ei;
    const int* dst = ei + EE;

    float *h, *as_, *ad_, *pool2;
    uint16_t *xhi, *xlo, *fhi, *flo, *bthi, *btlo;
    cudaGetSymbolAddress((void**)&h,     g_h);
    cudaGetSymbolAddress((void**)&as_,   g_as);
    cudaGetSymbolAddress((void**)&ad_,   g_ad);
    cudaGetSymbolAddress((void**)&pool2, g_pool2);
    cudaGetSymbolAddress((void**)&xhi,   g_xhi);
    cudaGetSymbolAddress((void**)&xlo,   g_xlo);
    cudaGetSymbolAddress((void**)&fhi,   g_fhi);
    cudaGetSymbolAddress((void**)&flo,   g_flo);
    cudaGetSymbolAddress((void**)&bthi,  g_bthi);
    cudaGetSymbolAddress((void**)&btlo,  g_btlo);

    cudaFuncSetAttribute(mma_gemm_k, cudaFuncAttributeMaxDynamicSharedMemorySize,
                         2 * BUF32 * sizeof(uint32_t));

    const int nb = (NN + 511) / 512;
    const int gb = (NN * 32 + 255) / 256;

    transpose_all_k<<<dim3(8, 8, 5), dim3(32, 8)>>>(W1, W2, W3, fcW1, fcW2);
    ve_all_k<<<1, 96>>>(We1, ae1, We2, ae2, We3, ae3);
    init_k<<<(NN + 255) / 256, 256>>>();
    xsplit_k<<<(NN * 32 + 255) / 256, 256>>>(x);
    hist_k<<<(EE + 255) / 256, 256>>>(dst);

    // layer 1 GEMM (fused node-att)
    launch_gemm(xhi, xlo, bthi, btlo, h, NN, 128, HC, nullptr, 0,
                as1, ad1, as_, ad_);

    // CSR tail
    scan1_k<<<nb, 512>>>();
    scan2_k<<<1, 128>>>(nb);
    scan3_k<<<(NN + 255) / 256, 256>>>();
    scatter_k<<<(EE + 255) / 256, 256>>>(src, dst, ea);

    gat_edge_k<8><<<gb, 256>>>(as_, ad_, h, b1, fhi, flo, 0);

    // layer 2
    launch_gemm(fhi, flo, bthi + 1 * 65536, btlo + 1 * 65536, h, NN, 256, HC,
                nullptr, 0, as2, ad2, as_, ad_);
    gat_edge_k<8><<<gb, 256>>>(as_, ad_, h, b2, fhi, flo, 40);

    // layer 3 (H=1: 8 partial slots, summed in edge kernel)
    launch_gemm(fhi, flo, bthi + 2 * 65536, btlo + 2 * 65536, h, NN, 256, HC,
                nullptr, 0, as3, ad3, as_, ad_);
    gat_edge_k<1><<<gb, 256>>>(as_, ad_, h, b3, fhi, flo, 80);

    // fc1 + gelu + pooling fused; then tiny (pool/cnt)@fc2
    launch_gemm(fhi, flo, bthi + 3 * 65536, btlo + 3 * 65536, nullptr, NN, 256, 256,
                fcb1, 1, nullptr, nullptr, nullptr, nullptr, pool2, batch);
    pool_fin2_k<<<GG, 256>>>(batch, bthi + 4 * 65536, btlo + 4 * 65536, fcb2,
                             (float*)d_out);
}

// round 13
// speedup vs baseline: 1.0493x; 1.0493x over previous
#include <cuda_runtime.h>
#include <cuda_bf16.h>
#include <math.h>
#include <stdint.h>

#define NN 50000
#define EE 400000
#define GG 64
#define HC 256

// ---------------- scratch (static device globals) ---------------------------
__device__ float    g_feat [NN * HC];
__device__ float    g_h    [NN * HC];
__device__ float    g_as   [NN * 8];
__device__ float    g_ad   [NN * 8];
__device__ float    g_VeAll[96];
__device__ float    g_pool2[GG * 256];
__device__ uint16_t g_bthi [5 * 256 * 256];   // pre-split transposed weights
__device__ uint16_t g_btlo [5 * 256 * 256];
// CSR
__device__ int   g_deg [NN];
__device__ int   g_rs  [NN];
__device__ int   g_wp  [NN];
__device__ int   g_part[128];
__device__ int   g_csrc[EE];
__device__ float g_cea [EE * 5];

// ---------------- helpers ---------------------------------------------------
__device__ __forceinline__ float elu1(float x) { return x > 0.0f ? x : expm1f(x); }
__device__ __forceinline__ float gelu1(float x) {
    return 0.5f * x * (1.0f + erff(x * 0.70710678118654752f));
}
__device__ __forceinline__ uint32_t bfpack(float lo_e, float hi_e) {
    uint32_t r;
    asm("cvt.rn.bf16x2.f32 %0, %1, %2;" : "=r"(r) : "f"(hi_e), "f"(lo_e));
    return r;
}
__device__ __forceinline__ uint16_t bf16of(float x) {
    uint16_t b;
    asm("cvt.rn.bf16.f32 %0, %1;" : "=h"(b) : "f"(x));
    return b;
}
__device__ __forceinline__ float f32of(uint16_t b) {
    float r;
    asm("cvt.f32.bf16 %0, %1;" : "=f"(r) : "h"(b));
    return r;
}
__device__ __forceinline__ float bfround(float x) { return f32of(bf16of(x)); }

__device__ __forceinline__ void mma_bf16(float* d, const uint32_t* a,
                                         uint32_t b0, uint32_t b1) {
    asm volatile(
        "mma.sync.aligned.m16n8k16.row.col.f32.bf16.bf16.f32 "
        "{%0,%1,%2,%3}, {%4,%5,%6,%7}, {%8,%9}, {%0,%1,%2,%3};"
        : "+f"(d[0]), "+f"(d[1]), "+f"(d[2]), "+f"(d[3])
        : "r"(a[0]), "r"(a[1]), "r"(a[2]), "r"(a[3]), "r"(b0), "r"(b1));
}

#define LDSM4(r, addr) \
    asm volatile("ldmatrix.sync.aligned.m8n8.x4.shared.b16 {%0,%1,%2,%3}, [%4];" \
        : "=r"((r)[0]), "=r"((r)[1]), "=r"((r)[2]), "=r"((r)[3]) : "r"(addr))

// ---------------- warp-MMA 3xBF16 GEMM, 128x128 CTA tile ---------------------
// A fp32 (split on the fly), B pre-split bf16 hi/lo.
#define S32 12
#define TILE32 (128 * S32)
#define BUF32 (4 * TILE32)

__global__ void __launch_bounds__(256, 2)
mma_gemm_k(const float* __restrict__ A,
           const uint16_t* __restrict__ Bhi, const uint16_t* __restrict__ Blo,
           float* __restrict__ C, int Nrows, int K, int ncols,
           const float* __restrict__ bias, int act,
           const float* __restrict__ att_s, const float* __restrict__ att_d,
           float* __restrict__ as_out, float* __restrict__ ad_out,
           float* __restrict__ pool_out, const int* __restrict__ batchv)
{
    extern __shared__ uint32_t sm32[];
    uint32_t sbase;
    asm("{ .reg .u64 t; cvta.to.shared.u64 t, %1; cvt.u32.u64 %0, t; }"
        : "=r"(sbase) : "l"(sm32));

    const int tid = threadIdx.x;
    const int lane = tid & 31, wid = tid >> 5;
    const int wr = wid >> 2, wc = wid & 3;
    const int tg = lane >> 2, tig = lane & 3;
    const int m0 = blockIdx.x * 128, n0 = blockIdx.y * 128;
    const int jcnt = max(0, min(4, (ncols - n0 - wc * 32 + 7) >> 3));

    const int lr = lane & 7, seg = lane >> 3;
    const uint32_t aoff = (uint32_t)((wr * 64 + lr + (seg & 1) * 8) * S32) * 4
                        + (uint32_t)(seg >> 1) * 16;
    const uint32_t boff = (uint32_t)((wc * 32 + (seg >> 1) * 8 + lr) * S32) * 4
                        + (uint32_t)(seg & 1) * 16;

    float acc[4][4][4];
    #pragma unroll
    for (int i = 0; i < 4; i++)
        #pragma unroll
        for (int j = 0; j < 4; j++)
            #pragma unroll
            for (int q = 0; q < 4; q++) acc[i][j][q] = 0.0f;

    const int nc = K / 16;
    float4 aReg[2];
    uint4 sBh, sBl;
    const int lrow = tid >> 1, lq = tid & 1;   // B staging map

    auto loadG = [&](int c) {
        const int k0 = c * 16;
        #pragma unroll
        for (int i = 0; i < 2; i++) {
            int idx = tid + i * 256;
            int r = idx >> 2, c4 = (idx & 3) * 4;
            int grow = m0 + r;
            aReg[i] = (grow < Nrows) ? *(const float4*)&A[(size_t)grow * K + k0 + c4]
                                     : make_float4(0.f, 0.f, 0.f, 0.f);
        }
        const uint4 z = make_uint4(0, 0, 0, 0);
        int gn = n0 + lrow;
        size_t bo = (size_t)gn * K + k0 + lq * 8;
        sBh = (gn < ncols) ? *(const uint4*)&Bhi[bo] : z;
        sBl = (gn < ncols) ? *(const uint4*)&Blo[bo] : z;
    };
    auto storeS = [&](int buf) {
        uint32_t* base = sm32 + buf * BUF32;
        #pragma unroll
        for (int i = 0; i < 2; i++) {
            int idx = tid + i * 256;
            int r = idx >> 2, p32 = (idx & 3) * 2;
            const float* av = (const float*)&aReg[i];
            float hx0 = bfround(av[0]), hx1 = bfround(av[1]);
            float hx2 = bfround(av[2]), hx3 = bfround(av[3]);
            uint2 ahi = make_uint2(bfpack(hx0, hx1), bfpack(hx2, hx3));
            uint2 alo = make_uint2(bfpack(av[0] - hx0, av[1] - hx1),
                                   bfpack(av[2] - hx2, av[3] - hx3));
            int o = r * S32 + p32;
            *(uint2*)(base + o)          = ahi;
            *(uint2*)(base + TILE32 + o) = alo;
        }
        int o = lrow * S32 + lq * 4;
        *(uint4*)(base + 2 * TILE32 + o) = sBh;
        *(uint4*)(base + 3 * TILE32 + o) = sBl;
    };
    auto compute = [&](int buf) {
        const uint32_t bb = sbase + (uint32_t)buf * BUF32 * 4;
        const uint32_t a_h = bb + aoff;
        const uint32_t a_l = a_h + TILE32 * 4;
        const uint32_t b_h = bb + 2 * TILE32 * 4 + boff;
        const uint32_t b_l = b_h + TILE32 * 4;

        uint32_t ah[4][4], al[4][4], bh[4][2], bl[4][2];
        #pragma unroll
        for (int i = 0; i < 4; i++) {
            LDSM4(ah[i], a_h + (uint32_t)(i * 16 * S32) * 4);
            LDSM4(al[i], a_l + (uint32_t)(i * 16 * S32) * 4);
        }
        #pragma unroll
        for (int jp = 0; jp < 2; jp++) {
            uint32_t t[4];
            LDSM4(t, b_h + (uint32_t)(jp * 16 * S32) * 4);
            bh[jp * 2][0] = t[0]; bh[jp * 2][1] = t[1];
            bh[jp * 2 + 1][0] = t[2]; bh[jp * 2 + 1][1] = t[3];
            LDSM4(t, b_l + (uint32_t)(jp * 16 * S32) * 4);
            bl[jp * 2][0] = t[0]; bl[jp * 2][1] = t[1];
            bl[jp * 2 + 1][0] = t[2]; bl[jp * 2 + 1][1] = t[3];
        }
        #pragma unroll
        for (int j = 0; j < 4; j++) {
            if (j >= jcnt) break;
            #pragma unroll
            for (int i = 0; i < 4; i++) {
                mma_bf16(acc[i][j], ah[i], bh[j][0], bh[j][1]);
                mma_bf16(acc[i][j], ah[i], bl[j][0], bl[j][1]);
                mma_bf16(acc[i][j], al[i], bh[j][0], bh[j][1]);
            }
        }
    };

    loadG(0); storeS(0);
    __syncthreads();
    for (int c = 0; c < nc; c++) {
        if (c + 1 < nc) loadG(c + 1);
        compute(c & 1);
        if (c + 1 < nc) storeS((c + 1) & 1);
        __syncthreads();
    }

    // ---- C store epilogue ----
    if (C) {
        #pragma unroll
        for (int i = 0; i < 4; i++) {
            int row = m0 + wr * 64 + i * 16 + tg;
            #pragma unroll
            for (int j = 0; j < 4; j++) {
                int col = n0 + wc * 32 + j * 8 + tig * 2;
                if (col >= ncols) continue;
                #pragma unroll
                for (int half = 0; half < 2; half++) {
                    int r = row + half * 8;
                    if (r >= Nrows) continue;
                    float v0 = acc[i][j][half * 2 + 0];
                    float v1 = acc[i][j][half * 2 + 1];
                    if (bias) { v0 += bias[col]; v1 += bias[col + 1]; }
                    if (act == 1) { v0 = gelu1(v0); v1 = gelu1(v1); }
                    *(float2*)&C[(size_t)r * ncols + col] = make_float2(v0, v1);
                }
            }
        }
    }

    // ---- fused node-attention dots (plain stores, 8-slot layout) ----
    if (as_out) {
        const int slot = (n0 >> 5) + wc;
        #pragma unroll
        for (int i = 0; i < 4; i++) {
            float s1 = 0.f, d1 = 0.f, s2 = 0.f, d2 = 0.f;
            #pragma unroll
            for (int j = 0; j < 4; j++) {
                int col = n0 + wc * 32 + j * 8 + tig * 2;
                float a0 = att_s[col], a1 = att_s[col + 1];
                float b0 = att_d[col], b1 = att_d[col + 1];
                s1 += acc[i][j][0] * a0 + acc[i][j][1] * a1;
                d1 += acc[i][j][0] * b0 + acc[i][j][1] * b1;
                s2 += acc[i][j][2] * a0 + acc[i][j][3] * a1;
                d2 += acc[i][j][2] * b0 + acc[i][j][3] * b1;
            }
            s1 += __shfl_xor_sync(0xffffffffu, s1, 1); s1 += __shfl_xor_sync(0xffffffffu, s1, 2);
            d1 += __shfl_xor_sync(0xffffffffu, d1, 1); d1 += __shfl_xor_sync(0xffffffffu, d1, 2);
            s2 += __shfl_xor_sync(0xffffffffu, s2, 1); s2 += __shfl_xor_sync(0xffffffffu, s2, 2);
            d2 += __shfl_xor_sync(0xffffffffu, d2, 1); d2 += __shfl_xor_sync(0xffffffffu, d2, 2);
            if (tig == 0) {
                int r1 = m0 + wr * 64 + i * 16 + tg;
                int r2 = r1 + 8;
                if (r1 < Nrows) { as_out[r1 * 8 + slot] = s1; ad_out[r1 * 8 + slot] = d1; }
                if (r2 < Nrows) { as_out[r2 * 8 + slot] = s2; ad_out[r2 * 8 + slot] = d2; }
            }
        }
    }

    // ---- fused gelu + segment-sum pooling (fc1 + pool) ----
    if (pool_out) {
        const int rbase = m0 + wr * 64;
        bool uniform = (rbase + 63 < Nrows) && (batchv[rbase] == batchv[rbase + 63]);
        if (uniform) {
            int g = batchv[rbase];
            #pragma unroll
            for (int j = 0; j < 4; j++) {
                #pragma unroll
                for (int qc = 0; qc < 2; qc++) {
                    int col = n0 + wc * 32 + j * 8 + tig * 2 + qc;
                    float sum = 0.f;
                    #pragma unroll
                    for (int i = 0; i < 4; i++)
                        #pragma unroll
                        for (int half = 0; half < 2; half++)
                            sum += gelu1(acc[i][j][half * 2 + qc] + bias[col]);
                    atomicAdd(&pool_out[g * 256 + col], sum);
                }
            }
        } else {
            #pragma unroll
            for (int i = 0; i < 4; i++)
                #pragma unroll
                for (int j = 0; j < 4; j++)
                    #pragma unroll
                    for (int q = 0; q < 4; q++) {
                        int r = rbase + i * 16 + tg + (q >> 1) * 8;
                        if (r >= Nrows) continue;
                        int col = n0 + wc * 32 + j * 8 + tig * 2 + (q & 1);
                        float v = gelu1(acc[i][j][q] + bias[col]);
                        atomicAdd(&pool_out[batchv[r] * 256 + col], v);
                    }
        }
    }
}

// ---------------- batched weight transpose + split (all 5 at once) ----------
__global__ void transpose_all_k(const float* __restrict__ W1, const float* __restrict__ W2,
                                const float* __restrict__ W3, const float* __restrict__ f1,
                                const float* __restrict__ f2)
{
    __shared__ float t[32][33];
    int z = blockIdx.z;
    const float* W = (z == 0) ? W1 : (z == 1) ? W2 : (z == 2) ? W3 : (z == 3) ? f1 : f2;
    int K = (z == 0) ? 128 : 256;
    int M = (z == 4) ? 32 : 256;
    uint16_t* Bh = g_bthi + z * 65536;
    uint16_t* Bl = g_btlo + z * 65536;
    int m0 = blockIdx.x * 32, k0 = blockIdx.y * 32;
    if (m0 >= M || k0 >= K) return;
    for (int i = threadIdx.y; i < 32; i += 8) {
        int k = k0 + i, m = m0 + threadIdx.x;
        t[i][threadIdx.x] = (k < K && m < M) ? W[(size_t)k * M + m] : 0.f;
    }
    __syncthreads();
    for (int i = threadIdx.y; i < 32; i += 8) {
        int m = m0 + i, k = k0 + threadIdx.x;
        if (m < M && k < K) {
            float v = t[threadIdx.x][i];
            uint16_t hi = bf16of(v);
            Bh[(size_t)m * K + k] = hi;
            Bl[(size_t)m * K + k] = bf16of(v - f32of(hi));
        }
    }
}

// ---------------- batched Ve ---------------------------------------------------
__global__ void ve_all_k(const float* __restrict__ We1, const float* __restrict__ ae1,
                         const float* __restrict__ We2, const float* __restrict__ ae2,
                         const float* __restrict__ We3, const float* __restrict__ ae3)
{
    int tid = threadIdx.x;
    const float* We; const float* ae; int H, base, loc;
    if (tid < 40)      { We = We1; ae = ae1; H = 8; base = 0;  loc = tid; }
    else if (tid < 80) { We = We2; ae = ae2; H = 8; base = 40; loc = tid - 40; }
    else if (tid < 85) { We = We3; ae = ae3; H = 1; base = 80; loc = tid - 80; }
    else return;
    int d = loc / H, h = loc % H;
    int C = 256 / H;
    float s = 0.0f;
    for (int c = 0; c < C; c++) s += We[d * 256 + h * C + c] * ae[h * C + c];
    g_VeAll[base + loc] = s;
}

// ---------------- init ----------------------------------------------------------
__global__ void init_k()
{
    int i = blockIdx.x * blockDim.x + threadIdx.x;
    if (i < NN) g_deg[i] = 0;
    if (i < GG * 256) g_pool2[i] = 0.0f;
}

// ---------------- CSR build ------------------------------------------------------
__global__ void hist_k(const int* __restrict__ dst)
{
    int e = blockIdx.x * blockDim.x + threadIdx.x;
    if (e < EE) atomicAdd(&g_deg[dst[e]], 1);
}
__global__ void scan1_k()
{
    __shared__ int s[512];
    int tid = threadIdx.x;
    int i = blockIdx.x * 512 + tid;
    int v = (i < NN) ? g_deg[i] : 0;
    s[tid] = v;
    __syncthreads();
    for (int off = 1; off < 512; off <<= 1) {
        int t = (tid >= off) ? s[tid - off] : 0;
        __syncthreads();
        s[tid] += t;
        __syncthreads();
    }
    if (i < NN) g_rs[i] = s[tid] - v;
    if (tid == 511) g_part[blockIdx.x] = s[511];
}
__global__ void scan2_k(int nb)
{
    __shared__ int s[128];
    int tid = threadIdx.x;
    int v = (tid < nb) ? g_part[tid] : 0;
    s[tid] = v;
    __syncthreads();
    for (int off = 1; off < 128; off <<= 1) {
        int t = (tid >= off) ? s[tid - off] : 0;
        __syncthreads();
        s[tid] += t;
        __syncthreads();
    }
    if (tid < nb) g_part[tid] = s[tid] - v;
}
__global__ void scan3_k()
{
    int i = blockIdx.x * blockDim.x + threadIdx.x;
    if (i >= NN) return;
    int r = g_rs[i] + g_part[i >> 9];
    g_rs[i] = r;
    g_wp[i] = r;
}
__global__ void scatter_k(const int* __restrict__ src, const int* __restrict__ dst,
                          const float* __restrict__ ea)
{
    int e = blockIdx.x * blockDim.x + threadIdx.x;
    if (e >= EE) return;
    int d = dst[e];
    int pos = atomicAdd(&g_wp[d], 1);
    g_csrc[pos] = src[e];
    #pragma unroll
    for (int i = 0; i < 5; i++) g_cea[(size_t)pos * 5 + i] = ea[(size_t)e * 5 + i];
}

// ---------------- fused single-pass edge softmax + aggregation ---------------
template <int H>
__global__ void __launch_bounds__(256)
gat_edge_k(const float* __restrict__ as_, const float* __restrict__ ad_,
           const float* __restrict__ hfeat, const float* __restrict__ bias,
           float* __restrict__ outf, int veBase)
{
    int w = (blockIdx.x * blockDim.x + threadIdx.x) >> 5;
    if (w >= NN) return;
    int lane = threadIdx.x & 31;
    const int head = (H == 8) ? (lane >> 2) : 0;
    const int tig = lane & 3;
    const int col0 = lane * 8;

    float ve[5];
    #pragma unroll
    for (int i = 0; i < 5; i++) ve[i] = g_VeAll[veBase + i * H + head];

    float adv;
    if (H == 1) {
        float4 a0 = *(const float4*)&ad_[w * 8];
        float4 a1 = *(const float4*)&ad_[w * 8 + 4];
        adv = a0.x + a0.y + a0.z + a0.w + a1.x + a1.y + a1.z + a1.w;
    } else {
        adv = ad_[w * 8 + head];
    }
    const int r0 = g_rs[w], dg = g_deg[w];

    float den = 0.0f;
    float acc[8];
    #pragma unroll
    for (int q = 0; q < 8; q++) acc[q] = 0.0f;

    for (int j = 0; j < dg; j += 4) {
        int jj = j + tig;
        bool valid = jj < dg;
        int je = r0 + (valid ? jj : 0);
        int sq = g_csrc[je];
        const float* ce = g_cea + (size_t)je * 5;
        float asv;
        if (H == 1) {
            float4 a0 = *(const float4*)&as_[sq * 8];
            float4 a1 = *(const float4*)&as_[sq * 8 + 4];
            asv = a0.x + a0.y + a0.z + a0.w + a1.x + a1.y + a1.z + a1.w;
        } else {
            asv = as_[sq * 8 + head];
        }
        float a = asv + adv;
        #pragma unroll
        for (int i = 0; i < 5; i++) a = fmaf(ce[i], ve[i], a);
        a = a > 0.0f ? a : 0.2f * a;
        float pq = valid ? __expf(a) : 0.0f;
        #pragma unroll
        for (int q = 0; q < 4; q++) {
            float p = __shfl_sync(0xffffffffu, pq, (lane & ~3) | q);
            int s   = __shfl_sync(0xffffffffu, sq, q);
            if (p != 0.0f) {
                den += p;
                const float4* hp = (const float4*)(hfeat + (size_t)s * 256 + col0);
                float4 v0 = hp[0], v1 = hp[1];
                acc[0] = fmaf(p, v0.x, acc[0]); acc[1] = fmaf(p, v0.y, acc[1]);
                acc[2] = fmaf(p, v0.z, acc[2]); acc[3] = fmaf(p, v0.w, acc[3]);
                acc[4] = fmaf(p, v1.x, acc[4]); acc[5] = fmaf(p, v1.y, acc[5]);
                acc[6] = fmaf(p, v1.z, acc[6]); acc[7] = fmaf(p, v1.w, acc[7]);
            }
        }
    }

    float inv = 1.0f / (den + 1e-16f);
    float4 o0, o1;
    float* op = (float*)&o0;
    #pragma unroll
    for (int q = 0; q < 4; q++) op[q] = elu1(acc[q] * inv + bias[col0 + q]);
    op = (float*)&o1;
    #pragma unroll
    for (int q = 0; q < 4; q++) op[q] = elu1(acc[4 + q] * inv + bias[col0 + 4 + q]);
    *(float4*)&outf[(size_t)w * 256 + col0]     = o0;
    *(float4*)&outf[(size_t)w * 256 + col0 + 4] = o1;
}

// ---------------- final: out[g] = (pool2[g]/cnt[g]) @ fc2^T + b ----------------
__global__ void pool_fin2_k(const int* __restrict__ batch,
                            const uint16_t* __restrict__ fc2thi,
                            const uint16_t* __restrict__ fc2tlo,
                            const float* __restrict__ fcb2,
                            float* __restrict__ out)
{
    __shared__ float v[256];
    __shared__ float sinv;
    int g = blockIdx.x, t = threadIdx.x;
    if (t == 0) {
        int a = 0, b = NN;
        while (a < b) { int m = (a + b) >> 1; if (batch[m] < g) a = m + 1; else b = m; }
        int lo = a;
        a = lo; b = NN;
        while (a < b) { int m = (a + b) >> 1; if (batch[m] < g + 1) a = m + 1; else b = m; }
        sinv = 1.0f / fmaxf((float)(a - lo), 1.0f);
    }
    __syncthreads();
    v[t] = g_pool2[g * 256 + t] * sinv;
    __syncthreads();
    if (t < 32) {
        float s = fcb2[t];
        const uint16_t* wh = fc2thi + t * 256;
        const uint16_t* wl = fc2tlo + t * 256;
        #pragma unroll 8
        for (int k = 0; k < 256; k++)
            s = fmaf(v[k], f32of(wh[k]) + f32of(wl[k]), s);
        out[g * 32 + t] = s;
    }
}

// ============================================================================
static void launch_gemm(const float* A, const uint16_t* bhi, const uint16_t* blo,
                        float* C, int n, int K, int ncols, const float* bias, int act,
                        const float* att_s = nullptr, const float* att_d = nullptr,
                        float* as_o = nullptr, float* ad_o = nullptr,
                        float* pool_o = nullptr, const int* batchv = nullptr)
{
    dim3 grid((n + 127) / 128, (ncols + 127) / 128);
    mma_gemm_k<<<grid, 256, 2 * BUF32 * sizeof(uint32_t)>>>(
        A, bhi, blo, C, n, K, ncols, bias, act, att_s, att_d, as_o, ad_o, pool_o, batchv);
}

extern "C" void kernel_launch(void* const* d_in, const int* in_sizes, int n_in,
                              void* d_out, int out_size)
{
    const float* x     = (const float*)d_in[0];
    const int*   ei    = (const int*)  d_in[1];
    const float* ea    = (const float*)d_in[2];
    const int*   batch = (const int*)  d_in[3];
    const float* W1  = (const float*)d_in[4];
    const float* as1 = (const float*)d_in[5];
    const float* ad1 = (const float*)d_in[6];
    const float* We1 = (const float*)d_in[7];
    const float* ae1 = (const float*)d_in[8];
    const float* b1  = (const float*)d_in[9];
    const float* W2  = (const float*)d_in[10];
    const float* as2 = (const float*)d_in[11];
    const float* ad2 = (const float*)d_in[12];
    const float* We2 = (const float*)d_in[13];
    const float* ae2 = (const float*)d_in[14];
    const float* b2  = (const float*)d_in[15];
    const float* W3  = (const float*)d_in[16];
    const float* as3 = (const float*)d_in[17];
    const float* ad3 = (const float*)d_in[18];
    const float* We3 = (const float*)d_in[19];
    const float* ae3 = (const float*)d_in[20];
    const float* b3  = (const float*)d_in[21];
    const float* fcW1 = (const float*)d_in[22];
    const float* fcb1 = (const float*)d_in[23];
    const float* fcW2 = (const float*)d_in[24];
    const float* fcb2 = (const float*)d_in[25];

    const int* src = ei;
    const int* dst = ei + EE;

    float *feat, *h, *as_, *ad_, *pool2;
    uint16_t *bthi, *btlo;
    cudaGetSymbolAddress((void**)&feat,  g_feat);
    cudaGetSymbolAddress((void**)&h,     g_h);
    cudaGetSymbolAddress((void**)&as_,   g_as);
    cudaGetSymbolAddress((void**)&ad_,   g_ad);
    cudaGetSymbolAddress((void**)&pool2, g_pool2);
    cudaGetSymbolAddress((void**)&bthi,  g_bthi);
    cudaGetSymbolAddress((void**)&btlo,  g_btlo);

    cudaFuncSetAttribute(mma_gemm_k, cudaFuncAttributeMaxDynamicSharedMemorySize,
                         2 * BUF32 * sizeof(uint32_t));

    const int nb = (NN + 511) / 512;
    const int gb = (NN * 32 + 255) / 256;

    transpose_all_k<<<dim3(8, 8, 5), dim3(32, 8)>>>(W1, W2, W3, fcW1, fcW2);
    ve_all_k<<<1, 96>>>(We1, ae1, We2, ae2, We3, ae3);
    init_k<<<(NN + 255) / 256, 256>>>();
    hist_k<<<(EE + 255) / 256, 256>>>(dst);

    // layer 1 GEMM (fused node-att)
    launch_gemm(x, bthi, btlo, h, NN, 128, HC, nullptr, 0, as1, ad1, as_, ad_);

    // CSR tail
    scan1_k<<<nb, 512>>>();
    scan2_k<<<1, 128>>>(nb);
    scan3_k<<<(NN + 255) / 256, 256>>>();
    scatter_k<<<(EE + 255) / 256, 256>>>(src, dst, ea);

    gat_edge_k<8><<<gb, 256>>>(as_, ad_, h, b1, feat, 0);

    // layer 2
    launch_gemm(feat, bthi + 1 * 65536, btlo + 1 * 65536, h, NN, 256, HC,
                nullptr, 0, as2, ad2, as_, ad_);
    gat_edge_k<8><<<gb, 256>>>(as_, ad_, h, b2, feat, 40);

    // layer 3 (H=1: 8 partial slots, summed in edge kernel)
    launch_gemm(feat, bthi + 2 * 65536, btlo + 2 * 65536, h, NN, 256, HC,
                nullptr, 0, as3, ad3, as_, ad_);
    gat_edge_k<1><<<gb, 256>>>(as_, ad_, h, b3, feat, 80);

    // fc1 + gelu + pooling fused; then tiny (pool/cnt)@fc2
    launch_gemm(feat, bthi + 3 * 65536, btlo + 3 * 65536, nullptr, NN, 256, 256,
                fcb1, 1, nullptr, nullptr, nullptr, nullptr, pool2, batch);
    pool_fin2_k<<<GG, 256>>>(batch, bthi + 4 * 65536, btlo + 4 * 65536, fcb2,
                             (float*)d_out);
}

// round 14
// speedup vs baseline: 1.1102x; 1.0581x over previous
#include <cuda_runtime.h>
#include <cuda_bf16.h>
#include <math.h>
#include <stdint.h>

#define NN 50000
#define EE 400000
#define GG 64
#define HC 256

// ---------------- scratch (static device globals) ---------------------------
__device__ float g_feat [NN * HC];
__device__ float g_h    [NN * HC];
__device__ float g_as   [NN * 8];
__device__ float g_ad   [NN * 8];
__device__ float g_VeAll[96];
__device__ float g_pool2[GG * 256];
__device__ float g_btall[5 * 256 * 256];
// CSR
__device__ int   g_deg [NN];
__device__ int   g_rs  [NN];
__device__ int   g_wp  [NN];
__device__ int   g_part[128];
__device__ int   g_csrc[EE];
__device__ float g_cea [EE * 5];

// ---------------- helpers ---------------------------------------------------
__device__ __forceinline__ float elu1(float x) { return x > 0.0f ? x : expm1f(x); }
__device__ __forceinline__ float gelu1(float x) {
    return 0.5f * x * (1.0f + erff(x * 0.70710678118654752f));
}

__device__ __forceinline__ uint32_t bfpack(float lo_e, float hi_e) {
    uint32_t r;
    asm("cvt.rn.bf16x2.f32 %0, %1, %2;" : "=r"(r) : "f"(hi_e), "f"(lo_e));
    return r;
}
__device__ __forceinline__ float bfround(float x) {
    uint16_t b;
    asm("cvt.rn.bf16.f32 %0, %1;" : "=h"(b) : "f"(x));
    float r;
    asm("cvt.f32.bf16 %0, %1;" : "=f"(r) : "h"(b));
    return r;
}

__device__ __forceinline__ void mma_bf16(float* d, const uint32_t* a,
                                         uint32_t b0, uint32_t b1) {
    asm volatile(
        "mma.sync.aligned.m16n8k16.row.col.f32.bf16.bf16.f32 "
        "{%0,%1,%2,%3}, {%4,%5,%6,%7}, {%8,%9}, {%0,%1,%2,%3};"
        : "+f"(d[0]), "+f"(d[1]), "+f"(d[2]), "+f"(d[3])
        : "r"(a[0]), "r"(a[1]), "r"(a[2]), "r"(a[3]), "r"(b0), "r"(b1));
}

#define LDSM4(r, addr) \
    asm volatile("ldmatrix.sync.aligned.m8n8.x4.shared.b16 {%0,%1,%2,%3}, [%4];" \
        : "=r"((r)[0]), "=r"((r)[1]), "=r"((r)[2]), "=r"((r)[3]) : "r"(addr))

// ---------------- warp-MMA 3xBF16 GEMM, 128x128 CTA tile ---------------------
#define S32 12
#define TILE32 (128 * S32)
#define BUF32 (4 * TILE32)

__global__ void __launch_bounds__(256, 2)
mma_gemm_k(const float* __restrict__ A, const float* __restrict__ Bt,
           float* __restrict__ C, int Nrows, int K, int ncols,
           const float* __restrict__ bias, int act,
           const float* __restrict__ att_s, const float* __restrict__ att_d,
           float* __restrict__ as_out, float* __restrict__ ad_out,
           float* __restrict__ pool_out, const int* __restrict__ batchv)
{
    extern __shared__ uint32_t sm32[];
    uint32_t sbase;
    asm("{ .reg .u64 t; cvta.to.shared.u64 t, %1; cvt.u32.u64 %0, t; }"
        : "=r"(sbase) : "l"(sm32));

    const int tid = threadIdx.x;
    const int lane = tid & 31, wid = tid >> 5;
    const int wr = wid >> 2, wc = wid & 3;
    const int tg = lane >> 2, tig = lane & 3;
    const int m0 = blockIdx.x * 128, n0 = blockIdx.y * 128;
    const int jcnt = max(0, min(4, (ncols - n0 - wc * 32 + 7) >> 3));

    const int lr = lane & 7, seg = lane >> 3;
    const uint32_t aoff = (uint32_t)((wr * 64 + lr + (seg & 1) * 8) * S32) * 4
                        + (uint32_t)(seg >> 1) * 16;
    const uint32_t boff = (uint32_t)((wc * 32 + (seg >> 1) * 8 + lr) * S32) * 4
                        + (uint32_t)(seg & 1) * 16;

    float acc[4][4][4];
    #pragma unroll
    for (int i = 0; i < 4; i++)
        #pragma unroll
        for (int j = 0; j < 4; j++)
            #pragma unroll
            for (int q = 0; q < 4; q++) acc[i][j][q] = 0.0f;

    const int nc = K / 16;
    float4 aReg[2], bReg[2];

    auto loadG = [&](int c) {
        const int k0 = c * 16;
        #pragma unroll
        for (int i = 0; i < 2; i++) {
            int idx = tid + i * 256;
            int r = idx >> 2, c4 = (idx & 3) * 4;
            int grow = m0 + r;
            aReg[i] = (grow < Nrows) ? *(const float4*)&A[(size_t)grow * K + k0 + c4]
                                     : make_float4(0.f, 0.f, 0.f, 0.f);
            int gn = n0 + r;
            bReg[i] = (gn < ncols) ? *(const float4*)&Bt[(size_t)gn * K + k0 + c4]
                                   : make_float4(0.f, 0.f, 0.f, 0.f);
        }
    };
    auto storeS = [&](int buf) {
        uint32_t* base = sm32 + buf * BUF32;
        #pragma unroll
        for (int i = 0; i < 2; i++) {
            int idx = tid + i * 256;
            int r = idx >> 2, p32 = (idx & 3) * 2;
            const float* av = (const float*)&aReg[i];
            const float* bv = (const float*)&bReg[i];
            float hx0 = bfround(av[0]), hx1 = bfround(av[1]);
            float hx2 = bfround(av[2]), hx3 = bfround(av[3]);
            uint2 ahi = make_uint2(bfpack(hx0, hx1), bfpack(hx2, hx3));
            uint2 alo = make_uint2(bfpack(av[0] - hx0, av[1] - hx1),
                                   bfpack(av[2] - hx2, av[3] - hx3));
            hx0 = bfround(bv[0]); hx1 = bfround(bv[1]);
            hx2 = bfround(bv[2]); hx3 = bfround(bv[3]);
            uint2 bhi = make_uint2(bfpack(hx0, hx1), bfpack(hx2, hx3));
            uint2 blo = make_uint2(bfpack(bv[0] - hx0, bv[1] - hx1),
                                   bfpack(bv[2] - hx2, bv[3] - hx3));
            int o = r * S32 + p32;
            *(uint2*)(base + o)              = ahi;
            *(uint2*)(base + TILE32 + o)     = alo;
            *(uint2*)(base + 2 * TILE32 + o) = bhi;
            *(uint2*)(base + 3 * TILE32 + o) = blo;
        }
    };
    auto compute = [&](int buf) {
        const uint32_t bb = sbase + (uint32_t)buf * BUF32 * 4;
        const uint32_t a_h = bb + aoff;
        const uint32_t a_l = a_h + TILE32 * 4;
        const uint32_t b_h = bb + 2 * TILE32 * 4 + boff;
        const uint32_t b_l = b_h + TILE32 * 4;

        uint32_t ah[4][4], al[4][4], bh[4][2], bl[4][2];
        #pragma unroll
        for (int i = 0; i < 4; i++) {
            LDSM4(ah[i], a_h + (uint32_t)(i * 16 * S32) * 4);
            LDSM4(al[i], a_l + (uint32_t)(i * 16 * S32) * 4);
        }
        #pragma unroll
        for (int jp = 0; jp < 2; jp++) {
            uint32_t t[4];
            LDSM4(t, b_h + (uint32_t)(jp * 16 * S32) * 4);
            bh[jp * 2][0] = t[0]; bh[jp * 2][1] = t[1];
            bh[jp * 2 + 1][0] = t[2]; bh[jp * 2 + 1][1] = t[3];
            LDSM4(t, b_l + (uint32_t)(jp * 16 * S32) * 4);
            bl[jp * 2][0] = t[0]; bl[jp * 2][1] = t[1];
            bl[jp * 2 + 1][0] = t[2]; bl[jp * 2 + 1][1] = t[3];
        }
        #pragma unroll
        for (int j = 0; j < 4; j++) {
            if (j >= jcnt) break;
            #pragma unroll
            for (int i = 0; i < 4; i++) {
                mma_bf16(acc[i][j], ah[i], bh[j][0], bh[j][1]);
                mma_bf16(acc[i][j], ah[i], bl[j][0], bl[j][1]);
                mma_bf16(acc[i][j], al[i], bh[j][0], bh[j][1]);
            }
        }
    };

    loadG(0); storeS(0);
    __syncthreads();
    for (int c = 0; c < nc; c++) {
        if (c + 1 < nc) loadG(c + 1);
        compute(c & 1);
        if (c + 1 < nc) storeS((c + 1) & 1);
        __syncthreads();
    }

    // ---- C store epilogue ----
    if (C) {
        #pragma unroll
        for (int i = 0; i < 4; i++) {
            int row = m0 + wr * 64 + i * 16 + tg;
            #pragma unroll
            for (int j = 0; j < 4; j++) {
                int col = n0 + wc * 32 + j * 8 + tig * 2;
                if (col >= ncols) continue;
                #pragma unroll
                for (int half = 0; half < 2; half++) {
                    int r = row + half * 8;
                    if (r >= Nrows) continue;
                    float v0 = acc[i][j][half * 2 + 0];
                    float v1 = acc[i][j][half * 2 + 1];
                    if (bias) { v0 += bias[col]; v1 += bias[col + 1]; }
                    if (act == 1) { v0 = gelu1(v0); v1 = gelu1(v1); }
                    *(float2*)&C[(size_t)r * ncols + col] = make_float2(v0, v1);
                }
            }
        }
    }

    // ---- fused node-attention dots (plain stores, 8-slot layout) ----
    if (as_out) {
        const int slot = (n0 >> 5) + wc;
        #pragma unroll
        for (int i = 0; i < 4; i++) {
            float s1 = 0.f, d1 = 0.f, s2 = 0.f, d2 = 0.f;
            #pragma unroll
            for (int j = 0; j < 4; j++) {
                int col = n0 + wc * 32 + j * 8 + tig * 2;
                float a0 = att_s[col], a1 = att_s[col + 1];
                float b0 = att_d[col], b1 = att_d[col + 1];
                s1 += acc[i][j][0] * a0 + acc[i][j][1] * a1;
                d1 += acc[i][j][0] * b0 + acc[i][j][1] * b1;
                s2 += acc[i][j][2] * a0 + acc[i][j][3] * a1;
                d2 += acc[i][j][2] * b0 + acc[i][j][3] * b1;
            }
            s1 += __shfl_xor_sync(0xffffffffu, s1, 1); s1 += __shfl_xor_sync(0xffffffffu, s1, 2);
            d1 += __shfl_xor_sync(0xffffffffu, d1, 1); d1 += __shfl_xor_sync(0xffffffffu, d1, 2);
            s2 += __shfl_xor_sync(0xffffffffu, s2, 1); s2 += __shfl_xor_sync(0xffffffffu, s2, 2);
            d2 += __shfl_xor_sync(0xffffffffu, d2, 1); d2 += __shfl_xor_sync(0xffffffffu, d2, 2);
            if (tig == 0) {
                int r1 = m0 + wr * 64 + i * 16 + tg;
                int r2 = r1 + 8;
                if (r1 < Nrows) { as_out[r1 * 8 + slot] = s1; ad_out[r1 * 8 + slot] = d1; }
                if (r2 < Nrows) { as_out[r2 * 8 + slot] = s2; ad_out[r2 * 8 + slot] = d2; }
            }
        }
    }

    // ---- fused gelu + segment-sum pooling (fc1 + pool) ----
    if (pool_out) {
        const int rbase = m0 + wr * 64;
        bool uniform = (rbase + 63 < Nrows) && (batchv[rbase] == batchv[rbase + 63]);
        if (uniform) {
            int g = batchv[rbase];
            #pragma unroll
            for (int j = 0; j < 4; j++) {
                #pragma unroll
                for (int qc = 0; qc < 2; qc++) {
                    int col = n0 + wc * 32 + j * 8 + tig * 2 + qc;
                    float sum = 0.f;
                    #pragma unroll
                    for (int i = 0; i < 4; i++)
                        #pragma unroll
                        for (int half = 0; half < 2; half++)
                            sum += gelu1(acc[i][j][half * 2 + qc] + bias[col]);
                    atomicAdd(&pool_out[g * 256 + col], sum);
                }
            }
        } else {
            #pragma unroll
            for (int i = 0; i < 4; i++)
                #pragma unroll
                for (int j = 0; j < 4; j++)
                    #pragma unroll
                    for (int q = 0; q < 4; q++) {
                        int r = rbase + i * 16 + tg + (q >> 1) * 8;
                        if (r >= Nrows) continue;
                        int col = n0 + wc * 32 + j * 8 + tig * 2 + (q & 1);
                        float v = gelu1(acc[i][j][q] + bias[col]);
                        atomicAdd(&pool_out[batchv[r] * 256 + col], v);
                    }
        }
    }
}

// ---------------- batched weight transpose (all 5 at once) -------------------
__global__ void transpose_all_k(const float* __restrict__ W1, const float* __restrict__ W2,
                                const float* __restrict__ W3, const float* __restrict__ f1,
                                const float* __restrict__ f2)
{
    __shared__ float t[32][33];
    int z = blockIdx.z;
    const float* W = (z == 0) ? W1 : (z == 1) ? W2 : (z == 2) ? W3 : (z == 3) ? f1 : f2;
    int K = (z == 0) ? 128 : 256;
    int M = (z == 4) ? 32 : 256;
    float* Bt = g_btall + z * 65536;
    int m0 = blockIdx.x * 32, k0 = blockIdx.y * 32;
    if (m0 >= M || k0 >= K) return;
    for (int i = threadIdx.y; i < 32; i += 8) {
        int k = k0 + i, m = m0 + threadIdx.x;
        t[i][threadIdx.x] = (k < K && m < M) ? W[(size_t)k * M + m] : 0.f;
    }
    __syncthreads();
    for (int i = threadIdx.y; i < 32; i += 8) {
        int m = m0 + i, k = k0 + threadIdx.x;
        if (m < M && k < K) Bt[(size_t)m * K + k] = t[threadIdx.x][i];
    }
}

// ---------------- batched Ve ---------------------------------------------------
__global__ void ve_all_k(const float* __restrict__ We1, const float* __restrict__ ae1,
                         const float* __restrict__ We2, const float* __restrict__ ae2,
                         const float* __restrict__ We3, const float* __restrict__ ae3)
{
    int tid = threadIdx.x;
    const float* We; const float* ae; int H, base, loc;
    if (tid < 40)      { We = We1; ae = ae1; H = 8; base = 0;  loc = tid; }
    else if (tid < 80) { We = We2; ae = ae2; H = 8; base = 40; loc = tid - 40; }
    else if (tid < 85) { We = We3; ae = ae3; H = 1; base = 80; loc = tid - 80; }
    else return;
    int d = loc / H, h = loc % H;
    int C = 256 / H;
    float s = 0.0f;
    for (int c = 0; c < C; c++) s += We[d * 256 + h * C + c] * ae[h * C + c];
    g_VeAll[base + loc] = s;
}

// ---------------- init ----------------------------------------------------------
__global__ void init_k()
{
    int i = blockIdx.x * blockDim.x + threadIdx.x;
    if (i < NN) g_deg[i] = 0;
    if (i < GG * 256) g_pool2[i] = 0.0f;
}

// ---------------- CSR build ------------------------------------------------------
__global__ void hist_k(const int* __restrict__ dst)
{
    int e = blockIdx.x * blockDim.x + threadIdx.x;
    if (e < EE) atomicAdd(&g_deg[dst[e]], 1);
}
__global__ void scan1_k()
{
    __shared__ int s[512];
    int tid = threadIdx.x;
    int i = blockIdx.x * 512 + tid;
    int v = (i < NN) ? g_deg[i] : 0;
    s[tid] = v;
    __syncthreads();
    for (int off = 1; off < 512; off <<= 1) {
        int t = (tid >= off) ? s[tid - off] : 0;
        __syncthreads();
        s[tid] += t;
        __syncthreads();
    }
    if (i < NN) g_rs[i] = s[tid] - v;
    if (tid == 511) g_part[blockIdx.x] = s[511];
}
__global__ void scan2_k(int nb)
{
    __shared__ int s[128];
    int tid = threadIdx.x;
    int v = (tid < nb) ? g_part[tid] : 0;
    s[tid] = v;
    __syncthreads();
    for (int off = 1; off < 128; off <<= 1) {
        int t = (tid >= off) ? s[tid - off] : 0;
        __syncthreads();
        s[tid] += t;
        __syncthreads();
    }
    if (tid < nb) g_part[tid] = s[tid] - v;
}
__global__ void scan3_k()
{
    int i = blockIdx.x * blockDim.x + threadIdx.x;
    if (i >= NN) return;
    int r = g_rs[i] + g_part[i >> 9];
    g_rs[i] = r;
    g_wp[i] = r;
}
__global__ void scatter_k(const int* __restrict__ src, const int* __restrict__ dst,
                          const float* __restrict__ ea)
{
    int e = blockIdx.x * blockDim.x + threadIdx.x;
    if (e >= EE) return;
    int d = dst[e];
    int pos = atomicAdd(&g_wp[d], 1);
    g_csrc[pos] = src[e];
    #pragma unroll
    for (int i = 0; i < 5; i++) g_cea[(size_t)pos * 5 + i] = ea[(size_t)e * 5 + i];
}

// ---------------- fused single-pass edge softmax + aggregation ---------------
template <int H>
__global__ void __launch_bounds__(256)
gat_edge_k(const float* __restrict__ as_, const float* __restrict__ ad_,
           const float* __restrict__ hfeat, const float* __restrict__ bias,
           float* __restrict__ outf, int veBase)
{
    int w = (blockIdx.x * blockDim.x + threadIdx.x) >> 5;
    if (w >= NN) return;
    int lane = threadIdx.x & 31;
    const int head = (H == 8) ? (lane >> 2) : 0;
    const int tig = lane & 3;
    const int col0 = lane * 8;

    float ve[5];
    #pragma unroll
    for (int i = 0; i < 5; i++) ve[i] = g_VeAll[veBase + i * H + head];

    float adv;
    if (H == 1) {
        float4 a0 = *(const float4*)&ad_[w * 8];
        float4 a1 = *(const float4*)&ad_[w * 8 + 4];
        adv = a0.x + a0.y + a0.z + a0.w + a1.x + a1.y + a1.z + a1.w;
    } else {
        adv = ad_[w * 8 + head];
    }
    const int r0 = g_rs[w], dg = g_deg[w];

    float den = 0.0f;
    float acc[8];
    #pragma unroll
    for (int q = 0; q < 8; q++) acc[q] = 0.0f;

    for (int j = 0; j < dg; j += 4) {
        int jj = j + tig;
        bool valid = jj < dg;
        int je = r0 + (valid ? jj : 0);
        int sq = g_csrc[je];
        const float* ce = g_cea + (size_t)je * 5;
        float asv;
        if (H == 1) {
            float4 a0 = *(const float4*)&as_[sq * 8];
            float4 a1 = *(const float4*)&as_[sq * 8 + 4];
            asv = a0.x + a0.y + a0.z + a0.w + a1.x + a1.y + a1.z + a1.w;
        } else {
            asv = as_[sq * 8 + head];
        }
        float a = asv + adv;
        #pragma unroll
        for (int i = 0; i < 5; i++) a = fmaf(ce[i], ve[i], a);
        a = a > 0.0f ? a : 0.2f * a;
        float pq = valid ? __expf(a) : 0.0f;
        #pragma unroll
        for (int q = 0; q < 4; q++) {
            float p = __shfl_sync(0xffffffffu, pq, (lane & ~3) | q);
            int s   = __shfl_sync(0xffffffffu, sq, q);
            if (p != 0.0f) {
                den += p;
                const float4* hp = (const float4*)(hfeat + (size_t)s * 256 + col0);
                float4 v0 = hp[0], v1 = hp[1];
                acc[0] = fmaf(p, v0.x, acc[0]); acc[1] = fmaf(p, v0.y, acc[1]);
                acc[2] = fmaf(p, v0.z, acc[2]); acc[3] = fmaf(p, v0.w, acc[3]);
                acc[4] = fmaf(p, v1.x, acc[4]); acc[5] = fmaf(p, v1.y, acc[5]);
                acc[6] = fmaf(p, v1.z, acc[6]); acc[7] = fmaf(p, v1.w, acc[7]);
            }
        }
    }

    float inv = 1.0f / (den + 1e-16f);
    float4 o0, o1;
    float* op = (float*)&o0;
    #pragma unroll
    for (int q = 0; q < 4; q++) op[q] = elu1(acc[q] * inv + bias[col0 + q]);
    op = (float*)&o1;
    #pragma unroll
    for (int q = 0; q < 4; q++) op[q] = elu1(acc[4 + q] * inv + bias[col0 + 4 + q]);
    *(float4*)&outf[(size_t)w * 256 + col0]     = o0;
    *(float4*)&outf[(size_t)w * 256 + col0 + 4] = o1;
}

// ---------------- final: out[g] = (pool2[g]/cnt[g]) @ fc2^T + b ----------------
__global__ void pool_fin2_k(const int* __restrict__ batch,
                            const float* __restrict__ fc2t,
                            const float* __restrict__ fcb2,
                            float* __restrict__ out)
{
    __shared__ float v[256];
    __shared__ float sinv;
    int g = blockIdx.x, t = threadIdx.x;
    if (t == 0) {
        int a = 0, b = NN;
        while (a < b) { int m = (a + b) >> 1; if (batch[m] < g) a = m + 1; else b = m; }
        int lo = a;
        a = lo; b = NN;
        while (a < b) { int m = (a + b) >> 1; if (batch[m] < g + 1) a = m + 1; else b = m; }
        sinv = 1.0f / fmaxf((float)(a - lo), 1.0f);
    }
    __syncthreads();
    v[t] = g_pool2[g * 256 + t] * sinv;
    __syncthreads();
    if (t < 32) {
        float s = fcb2[t];
        const float* wrow = fc2t + t * 256;
        #pragma unroll 8
        for (int k = 0; k < 256; k++) s = fmaf(v[k], wrow[k], s);
        out[g * 32 + t] = s;
    }
}

// ============================================================================
static void launch_gemm(const float* A, const float* bt, float* C,
                        int n, int K, int ncols, const float* bias, int act,
                        const float* att_s = nullptr, const float* att_d = nullptr,
                        float* as_o = nullptr, float* ad_o = nullptr,
                        float* pool_o = nullptr, const int* batchv = nullptr)
{
    dim3 grid((n + 127) / 128, (ncols + 127) / 128);
    mma_gemm_k<<<grid, 256, 2 * BUF32 * sizeof(uint32_t)>>>(
        A, bt, C, n, K, ncols, bias, act, att_s, att_d, as_o, ad_o, pool_o, batchv);
}

extern "C" void kernel_launch(void* const* d_in, const int* in_sizes, int n_in,
                              void* d_out, int out_size)
{
    const float* x     = (const float*)d_in[0];
    const int*   ei    = (const int*)  d_in[1];
    const float* ea    = (const float*)d_in[2];
    const int*   batch = (const int*)  d_in[3];
    const float* W1  = (const float*)d_in[4];
    const float* as1 = (const float*)d_in[5];
    const float* ad1 = (const float*)d_in[6];
    const float* We1 = (const float*)d_in[7];
    const float* ae1 = (const float*)d_in[8];
    const float* b1  = (const float*)d_in[9];
    const float* W2  = (const float*)d_in[10];
    const float* as2 = (const float*)d_in[11];
    const float* ad2 = (const float*)d_in[12];
    const float* We2 = (const float*)d_in[13];
    const float* ae2 = (const float*)d_in[14];
    const float* b2  = (const float*)d_in[15];
    const float* W3  = (const float*)d_in[16];
    const float* as3 = (const float*)d_in[17];
    const float* ad3 = (const float*)d_in[18];
    const float* We3 = (const float*)d_in[19];
    const float* ae3 = (const float*)d_in[20];
    const float* b3  = (const float*)d_in[21];
    const float* fcW1 = (const float*)d_in[22];
    const float* fcb1 = (const float*)d_in[23];
    const float* fcW2 = (const float*)d_in[24];
    const float* fcb2 = (const float*)d_in[25];

    const int* src = ei;
    const int* dst = ei + EE;

    float *feat, *h, *as_, *ad_, *btall, *pool2;
    cudaGetSymbolAddress((void**)&feat,  g_feat);
    cudaGetSymbolAddress((void**)&h,     g_h);
    cudaGetSymbolAddress((void**)&as_,   g_as);
    cudaGetSymbolAddress((void**)&ad_,   g_ad);
    cudaGetSymbolAddress((void**)&btall, g_btall);
    cudaGetSymbolAddress((void**)&pool2, g_pool2);

    cudaFuncSetAttribute(mma_gemm_k, cudaFuncAttributeMaxDynamicSharedMemorySize,
                         2 * BUF32 * sizeof(uint32_t));

    const int nb = (NN + 511) / 512;
    const int gb = (NN * 32 + 255) / 256;

    transpose_all_k<<<dim3(8, 8, 5), dim3(32, 8)>>>(W1, W2, W3, fcW1, fcW2);
    ve_all_k<<<1, 96>>>(We1, ae1, We2, ae2, We3, ae3);
    init_k<<<(NN + 255) / 256, 256>>>();
    hist_k<<<(EE + 255) / 256, 256>>>(dst);

    // layer 1 GEMM (fused node-att)
    launch_gemm(x, btall, h, NN, 128, HC, nullptr, 0, as1, ad1, as_, ad_);

    // CSR tail
    scan1_k<<<nb, 512>>>();
    scan2_k<<<1, 128>>>(nb);
    scan3_k<<<(NN + 255) / 256, 256>>>();
    scatter_k<<<(EE + 255) / 256, 256>>>(src, dst, ea);

    gat_edge_k<8><<<gb, 256>>>(as_, ad_, h, b1, feat, 0);

    // layer 2
    launch_gemm(feat, btall + 1 * 65536, h, NN, 256, HC, nullptr, 0, as2, ad2, as_, ad_);
    gat_edge_k<8><<<gb, 256>>>(as_, ad_, h, b2, feat, 40);

    // layer 3 (H=1: 8 partial slots, summed in edge kernel)
    launch_gemm(feat, btall + 2 * 65536, h, NN, 256, HC, nullptr, 0, as3, ad3, as_, ad_);
    gat_edge_k<1><<<gb, 256>>>(as_, ad_, h, b3, feat, 80);

    // fc1 + gelu + pooling fused; then tiny (pool/cnt)@fc2 with bsearch counts
    launch_gemm(feat, btall + 3 * 65536, nullptr, NN, 256, 256, fcb1, 1,
                nullptr, nullptr, nullptr, nullptr, pool2, batch);
    pool_fin2_k<<<GG, 256>>>(batch, btall + 4 * 65536, fcb2, (float*)d_out);
}

// round 15
// speedup vs baseline: 1.1107x; 1.0005x over previous
#include <cuda_runtime.h>
#include <cuda_bf16.h>
#include <math.h>
#include <stdint.h>

#define NN 50000
#define EE 400000
#define GG 64
#define HC 256

// ---------------- scratch (static device globals) ---------------------------
__device__ float g_feat [NN * HC];
__device__ float g_h    [NN * HC];
__device__ float g_as   [NN * 8];
__device__ float g_ad   [NN * 8];
__device__ float g_VeAll[96];
__device__ float g_pool2[GG * 256];
__device__ float g_btall[5 * 256 * 256];
// CSR
__device__ int   g_deg [NN];
__device__ int   g_rs  [NN];
__device__ int   g_wp  [NN];
__device__ int   g_part[128];
__device__ int   g_csrc[EE];
__device__ float g_cea [EE * 5];

// ---------------- helpers ---------------------------------------------------
__device__ __forceinline__ float elu1(float x) { return x > 0.0f ? x : expm1f(x); }
__device__ __forceinline__ float gelu1(float x) {
    return 0.5f * x * (1.0f + erff(x * 0.70710678118654752f));
}

__device__ __forceinline__ uint32_t bfpack(float lo_e, float hi_e) {
    uint32_t r;
    asm("cvt.rn.bf16x2.f32 %0, %1, %2;" : "=r"(r) : "f"(hi_e), "f"(lo_e));
    return r;
}
__device__ __forceinline__ float bfround(float x) {
    uint16_t b;
    asm("cvt.rn.bf16.f32 %0, %1;" : "=h"(b) : "f"(x));
    float r;
    asm("cvt.f32.bf16 %0, %1;" : "=f"(r) : "h"(b));
    return r;
}

__device__ __forceinline__ void mma_bf16(float* d, const uint32_t* a,
                                         uint32_t b0, uint32_t b1) {
    asm volatile(
        "mma.sync.aligned.m16n8k16.row.col.f32.bf16.bf16.f32 "
        "{%0,%1,%2,%3}, {%4,%5,%6,%7}, {%8,%9}, {%0,%1,%2,%3};"
        : "+f"(d[0]), "+f"(d[1]), "+f"(d[2]), "+f"(d[3])
        : "r"(a[0]), "r"(a[1]), "r"(a[2]), "r"(a[3]), "r"(b0), "r"(b1));
}

#define LDSM4(r, addr) \
    asm volatile("ldmatrix.sync.aligned.m8n8.x4.shared.b16 {%0,%1,%2,%3}, [%4];" \
        : "=r"((r)[0]), "=r"((r)[1]), "=r"((r)[2]), "=r"((r)[3]) : "r"(addr))

// ---------------- warp-MMA 3xBF16 GEMM, 128x128 CTA tile ---------------------
#define S32 12
#define TILE32 (128 * S32)
#define BUF32 (4 * TILE32)

__global__ void __launch_bounds__(256, 2)
mma_gemm_k(const float* __restrict__ A, const float* __restrict__ Bt,
           float* __restrict__ C, int Nrows, int K, int ncols,
           const float* __restrict__ bias, int act,
           const float* __restrict__ att_s, const float* __restrict__ att_d,
           float* __restrict__ as_out, float* __restrict__ ad_out,
           float* __restrict__ pool_out, const int* __restrict__ batchv)
{
    extern __shared__ uint32_t sm32[];
    uint32_t sbase;
    asm("{ .reg .u64 t; cvta.to.shared.u64 t, %1; cvt.u32.u64 %0, t; }"
        : "=r"(sbase) : "l"(sm32));

    const int tid = threadIdx.x;
    const int lane = tid & 31, wid = tid >> 5;
    const int wr = wid >> 2, wc = wid & 3;
    const int tg = lane >> 2, tig = lane & 3;
    const int m0 = blockIdx.x * 128, n0 = blockIdx.y * 128;
    const int jcnt = max(0, min(4, (ncols - n0 - wc * 32 + 7) >> 3));

    const int lr = lane & 7, seg = lane >> 3;
    const uint32_t aoff = (uint32_t)((wr * 64 + lr + (seg & 1) * 8) * S32) * 4
                        + (uint32_t)(seg >> 1) * 16;
    const uint32_t boff = (uint32_t)((wc * 32 + (seg >> 1) * 8 + lr) * S32) * 4
                        + (uint32_t)(seg & 1) * 16;

    float acc[4][4][4];
    #pragma unroll
    for (int i = 0; i < 4; i++)
        #pragma unroll
        for (int j = 0; j < 4; j++)
            #pragma unroll
            for (int q = 0; q < 4; q++) acc[i][j][q] = 0.0f;

    const int nc = K / 16;
    float4 aReg[2], bReg[2];

    auto loadG = [&](int c) {
        const int k0 = c * 16;
        #pragma unroll
        for (int i = 0; i < 2; i++) {
            int idx = tid + i * 256;
            int r = idx >> 2, c4 = (idx & 3) * 4;
            int grow = m0 + r;
            aReg[i] = (grow < Nrows) ? *(const float4*)&A[(size_t)grow * K + k0 + c4]
                                     : make_float4(0.f, 0.f, 0.f, 0.f);
            int gn = n0 + r;
            bReg[i] = (gn < ncols) ? *(const float4*)&Bt[(size_t)gn * K + k0 + c4]
                                   : make_float4(0.f, 0.f, 0.f, 0.f);
        }
    };
    auto storeS = [&](int buf) {
        uint32_t* base = sm32 + buf * BUF32;
        #pragma unroll
        for (int i = 0; i < 2; i++) {
            int idx = tid + i * 256;
            int r = idx >> 2, p32 = (idx & 3) * 2;
            const float* av = (const float*)&aReg[i];
            const float* bv = (const float*)&bReg[i];
            float hx0 = bfround(av[0]), hx1 = bfround(av[1]);
            float hx2 = bfround(av[2]), hx3 = bfround(av[3]);
            uint2 ahi = make_uint2(bfpack(hx0, hx1), bfpack(hx2, hx3));
            uint2 alo = make_uint2(bfpack(av[0] - hx0, av[1] - hx1),
                                   bfpack(av[2] - hx2, av[3] - hx3));
            hx0 = bfround(bv[0]); hx1 = bfround(bv[1]);
            hx2 = bfround(bv[2]); hx3 = bfround(bv[3]);
            uint2 bhi = make_uint2(bfpack(hx0, hx1), bfpack(hx2, hx3));
            uint2 blo = make_uint2(bfpack(bv[0] - hx0, bv[1] - hx1),
                                   bfpack(bv[2] - hx2, bv[3] - hx3));
            int o = r * S32 + p32;
            *(uint2*)(base + o)              = ahi;
            *(uint2*)(base + TILE32 + o)     = alo;
            *(uint2*)(base + 2 * TILE32 + o) = bhi;
            *(uint2*)(base + 3 * TILE32 + o) = blo;
        }
    };
    auto compute = [&](int buf) {
        const uint32_t bb = sbase + (uint32_t)buf * BUF32 * 4;
        const uint32_t a_h = bb + aoff;
        const uint32_t a_l = a_h + TILE32 * 4;
        const uint32_t b_h = bb + 2 * TILE32 * 4 + boff;
        const uint32_t b_l = b_h + TILE32 * 4;

        uint32_t ah[4][4], al[4][4], bh[4][2], bl[4][2];
        #pragma unroll
        for (int i = 0; i < 4; i++) {
            LDSM4(ah[i], a_h + (uint32_t)(i * 16 * S32) * 4);
            LDSM4(al[i], a_l + (uint32_t)(i * 16 * S32) * 4);
        }
        #pragma unroll
        for (int jp = 0; jp < 2; jp++) {
            uint32_t t[4];
            LDSM4(t, b_h + (uint32_t)(jp * 16 * S32) * 4);
            bh[jp * 2][0] = t[0]; bh[jp * 2][1] = t[1];
            bh[jp * 2 + 1][0] = t[2]; bh[jp * 2 + 1][1] = t[3];
            LDSM4(t, b_l + (uint32_t)(jp * 16 * S32) * 4);
            bl[jp * 2][0] = t[0]; bl[jp * 2][1] = t[1];
            bl[jp * 2 + 1][0] = t[2]; bl[jp * 2 + 1][1] = t[3];
        }
        #pragma unroll
        for (int j = 0; j < 4; j++) {
            if (j >= jcnt) break;
            #pragma unroll
            for (int i = 0; i < 4; i++) {
                mma_bf16(acc[i][j], ah[i], bh[j][0], bh[j][1]);
                mma_bf16(acc[i][j], ah[i], bl[j][0], bl[j][1]);
                mma_bf16(acc[i][j], al[i], bh[j][0], bh[j][1]);
            }
        }
    };

    loadG(0); storeS(0);
    __syncthreads();
    for (int c = 0; c < nc; c++) {
        if (c + 1 < nc) loadG(c + 1);
        compute(c & 1);
        if (c + 1 < nc) storeS((c + 1) & 1);
        __syncthreads();
    }

    // ---- C store epilogue ----
    if (C) {
        #pragma unroll
        for (int i = 0; i < 4; i++) {
            int row = m0 + wr * 64 + i * 16 + tg;
            #pragma unroll
            for (int j = 0; j < 4; j++) {
                int col = n0 + wc * 32 + j * 8 + tig * 2;
                if (col >= ncols) continue;
                #pragma unroll
                for (int half = 0; half < 2; half++) {
                    int r = row + half * 8;
                    if (r >= Nrows) continue;
                    float v0 = acc[i][j][half * 2 + 0];
                    float v1 = acc[i][j][half * 2 + 1];
                    if (bias) { v0 += bias[col]; v1 += bias[col + 1]; }
                    if (act == 1) { v0 = gelu1(v0); v1 = gelu1(v1); }
                    *(float2*)&C[(size_t)r * ncols + col] = make_float2(v0, v1);
                }
            }
        }
    }

    // ---- fused node-attention dots (plain stores, 8-slot layout) ----
    if (as_out) {
        const int slot = (n0 >> 5) + wc;
        #pragma unroll
        for (int i = 0; i < 4; i++) {
            float s1 = 0.f, d1 = 0.f, s2 = 0.f, d2 = 0.f;
            #pragma unroll
            for (int j = 0; j < 4; j++) {
                int col = n0 + wc * 32 + j * 8 + tig * 2;
                float a0 = att_s[col], a1 = att_s[col + 1];
                float b0 = att_d[col], b1 = att_d[col + 1];
                s1 += acc[i][j][0] * a0 + acc[i][j][1] * a1;
                d1 += acc[i][j][0] * b0 + acc[i][j][1] * b1;
                s2 += acc[i][j][2] * a0 + acc[i][j][3] * a1;
                d2 += acc[i][j][2] * b0 + acc[i][j][3] * b1;
            }
            s1 += __shfl_xor_sync(0xffffffffu, s1, 1); s1 += __shfl_xor_sync(0xffffffffu, s1, 2);
            d1 += __shfl_xor_sync(0xffffffffu, d1, 1); d1 += __shfl_xor_sync(0xffffffffu, d1, 2);
            s2 += __shfl_xor_sync(0xffffffffu, s2, 1); s2 += __shfl_xor_sync(0xffffffffu, s2, 2);
            d2 += __shfl_xor_sync(0xffffffffu, d2, 1); d2 += __shfl_xor_sync(0xffffffffu, d2, 2);
            if (tig == 0) {
                int r1 = m0 + wr * 64 + i * 16 + tg;
                int r2 = r1 + 8;
                if (r1 < Nrows) { as_out[r1 * 8 + slot] = s1; ad_out[r1 * 8 + slot] = d1; }
                if (r2 < Nrows) { as_out[r2 * 8 + slot] = s2; ad_out[r2 * 8 + slot] = d2; }
            }
        }
    }

    // ---- fused gelu + segment-sum pooling (fc1 + pool) ----
    if (pool_out) {
        const int rbase = m0 + wr * 64;
        bool uniform = (rbase + 63 < Nrows) && (batchv[rbase] == batchv[rbase + 63]);
        if (uniform) {
            int g = batchv[rbase];
            #pragma unroll
            for (int j = 0; j < 4; j++) {
                #pragma unroll
                for (int qc = 0; qc < 2; qc++) {
                    int col = n0 + wc * 32 + j * 8 + tig * 2 + qc;
                    float sum = 0.f;
                    #pragma unroll
                    for (int i = 0; i < 4; i++)
                        #pragma unroll
                        for (int half = 0; half < 2; half++)
                            sum += gelu1(acc[i][j][half * 2 + qc] + bias[col]);
                    atomicAdd(&pool_out[g * 256 + col], sum);
                }
            }
        } else {
            #pragma unroll
            for (int i = 0; i < 4; i++)
                #pragma unroll
                for (int j = 0; j < 4; j++)
                    #pragma unroll
                    for (int q = 0; q < 4; q++) {
                        int r = rbase + i * 16 + tg + (q >> 1) * 8;
                        if (r >= Nrows) continue;
                        int col = n0 + wc * 32 + j * 8 + tig * 2 + (q & 1);
                        float v = gelu1(acc[i][j][q] + bias[col]);
                        atomicAdd(&pool_out[batchv[r] * 256 + col], v);
                    }
        }
    }
}

// ---------------- batched weight transpose (all 5 at once) -------------------
__global__ void transpose_all_k(const float* __restrict__ W1, const float* __restrict__ W2,
                                const float* __restrict__ W3, const float* __restrict__ f1,
                                const float* __restrict__ f2)
{
    __shared__ float t[32][33];
    int z = blockIdx.z;
    const float* W = (z == 0) ? W1 : (z == 1) ? W2 : (z == 2) ? W3 : (z == 3) ? f1 : f2;
    int K = (z == 0) ? 128 : 256;
    int M = (z == 4) ? 32 : 256;
    float* Bt = g_btall + z * 65536;
    int m0 = blockIdx.x * 32, k0 = blockIdx.y * 32;
    if (m0 >= M || k0 >= K) return;
    for (int i = threadIdx.y; i < 32; i += 8) {
        int k = k0 + i, m = m0 + threadIdx.x;
        t[i][threadIdx.x] = (k < K && m < M) ? W[(size_t)k * M + m] : 0.f;
    }
    __syncthreads();
    for (int i = threadIdx.y; i < 32; i += 8) {
        int m = m0 + i, k = k0 + threadIdx.x;
        if (m < M && k < K) Bt[(size_t)m * K + k] = t[threadIdx.x][i];
    }
}

// ---------------- batched Ve ---------------------------------------------------
__global__ void ve_all_k(const float* __restrict__ We1, const float* __restrict__ ae1,
                         const float* __restrict__ We2, const float* __restrict__ ae2,
                         const float* __restrict__ We3, const float* __restrict__ ae3)
{
    int tid = threadIdx.x;
    const float* We; const float* ae; int H, base, loc;
    if (tid < 40)      { We = We1; ae = ae1; H = 8; base = 0;  loc = tid; }
    else if (tid < 80) { We = We2; ae = ae2; H = 8; base = 40; loc = tid - 40; }
    else if (tid < 85) { We = We3; ae = ae3; H = 1; base = 80; loc = tid - 80; }
    else return;
    int d = loc / H, h = loc % H;
    int C = 256 / H;
    float s = 0.0f;
    for (int c = 0; c < C; c++) s += We[d * 256 + h * C + c] * ae[h * C + c];
    g_VeAll[base + loc] = s;
}

// ---------------- init ----------------------------------------------------------
__global__ void init_k()
{
    int i = blockIdx.x * blockDim.x + threadIdx.x;
    if (i < NN) g_deg[i] = 0;
    if (i < GG * 256) g_pool2[i] = 0.0f;
}

// ---------------- CSR build ------------------------------------------------------
__global__ void hist_k(const int* __restrict__ dst)
{
    int e = blockIdx.x * blockDim.x + threadIdx.x;
    if (e < EE) atomicAdd(&g_deg[dst[e]], 1);
}
__global__ void scan1_k()
{
    __shared__ int s[512];
    int tid = threadIdx.x;
    int i = blockIdx.x * 512 + tid;
    int v = (i < NN) ? g_deg[i] : 0;
    s[tid] = v;
    __syncthreads();
    for (int off = 1; off < 512; off <<= 1) {
        int t = (tid >= off) ? s[tid - off] : 0;
        __syncthreads();
        s[tid] += t;
        __syncthreads();
    }
    if (i < NN) g_rs[i] = s[tid] - v;
    if (tid == 511) g_part[blockIdx.x] = s[511];
}
// scan3 with fused scan2: each CTA sums the block-partials it needs directly.
__global__ void scan3_k(int nb)
{
    __shared__ int sprefix;
    int i = blockIdx.x * blockDim.x + threadIdx.x;
    // CTA covers 256 consecutive nodes -> all within one or two scan1 blocks;
    // compute prefix of g_part for the scan1 block containing the CTA start.
    if (threadIdx.x == 0) {
        int myblk = (blockIdx.x * blockDim.x) >> 9;
        int s = 0;
        for (int k = 0; k < myblk; k++) s += g_part[k];
        sprefix = s;
    }
    __syncthreads();
    if (i >= NN) return;
    int blk = i >> 9;
    int mybase = (blockIdx.x * blockDim.x) >> 9;
    int pre = sprefix;
    if (blk != mybase) pre += g_part[blk - 1];   // CTA straddles one boundary max
    int r = g_rs[i] + pre;
    g_rs[i] = r;
    g_wp[i] = r;
}
__global__ void scatter_k(const int* __restrict__ src, const int* __restrict__ dst,
                          const float* __restrict__ ea)
{
    int e = blockIdx.x * blockDim.x + threadIdx.x;
    if (e >= EE) return;
    int d = dst[e];
    int pos = atomicAdd(&g_wp[d], 1);
    g_csrc[pos] = src[e];
    #pragma unroll
    for (int i = 0; i < 5; i++) g_cea[(size_t)pos * 5 + i] = ea[(size_t)e * 5 + i];
}

// ---------------- fused single-pass edge softmax + aggregation ---------------
template <int H>
__global__ void __launch_bounds__(256)
gat_edge_k(const float* __restrict__ as_, const float* __restrict__ ad_,
           const float* __restrict__ hfeat, const float* __restrict__ bias,
           float* __restrict__ outf, int veBase)
{
    int w = (blockIdx.x * blockDim.x + threadIdx.x) >> 5;
    if (w >= NN) return;
    int lane = threadIdx.x & 31;
    const int head = (H == 8) ? (lane >> 2) : 0;
    const int tig = lane & 3;
    const int col0 = lane * 8;

    float ve[5];
    #pragma unroll
    for (int i = 0; i < 5; i++) ve[i] = g_VeAll[veBase + i * H + head];

    float adv;
    if (H == 1) {
        float4 a0 = *(const float4*)&ad_[w * 8];
        float4 a1 = *(const float4*)&ad_[w * 8 + 4];
        adv = a0.x + a0.y + a0.z + a0.w + a1.x + a1.y + a1.z + a1.w;
    } else {
        adv = ad_[w * 8 + head];
    }
    const int r0 = g_rs[w], dg = g_deg[w];

    float den = 0.0f;
    float acc[8];
    #pragma unroll
    for (int q = 0; q < 8; q++) acc[q] = 0.0f;

    for (int j = 0; j < dg; j += 4) {
        int jj = j + tig;
        bool valid = jj < dg;
        int je = r0 + (valid ? jj : 0);
        int sq = g_csrc[je];
        const float* ce = g_cea + (size_t)je * 5;
        float asv;
        if (H == 1) {
            float4 a0 = *(const float4*)&as_[sq * 8];
            float4 a1 = *(const float4*)&as_[sq * 8 + 4];
            asv = a0.x + a0.y + a0.z + a0.w + a1.x + a1.y + a1.z + a1.w;
        } else {
            asv = as_[sq * 8 + head];
        }
        float a = asv + adv;
        #pragma unroll
        for (int i = 0; i < 5; i++) a = fmaf(ce[i], ve[i], a);
        a = a > 0.0f ? a : 0.2f * a;
        float pq = valid ? __expf(a) : 0.0f;
        #pragma unroll
        for (int q = 0; q < 4; q++) {
            float p = __shfl_sync(0xffffffffu, pq, (lane & ~3) | q);
            int s   = __shfl_sync(0xffffffffu, sq, q);
            if (p != 0.0f) {
                den += p;
                const float4* hp = (const float4*)(hfeat + (size_t)s * 256 + col0);
                float4 v0 = hp[0], v1 = hp[1];
                acc[0] = fmaf(p, v0.x, acc[0]); acc[1] = fmaf(p, v0.y, acc[1]);
                acc[2] = fmaf(p, v0.z, acc[2]); acc[3] = fmaf(p, v0.w, acc[3]);
                acc[4] = fmaf(p, v1.x, acc[4]); acc[5] = fmaf(p, v1.y, acc[5]);
                acc[6] = fmaf(p, v1.z, acc[6]); acc[7] = fmaf(p, v1.w, acc[7]);
            }
        }
    }

    float inv = 1.0f / (den + 1e-16f);
    float4 o0, o1;
    float* op = (float*)&o0;
    #pragma unroll
    for (int q = 0; q < 4; q++) op[q] = elu1(acc[q] * inv + bias[col0 + q]);
    op = (float*)&o1;
    #pragma unroll
    for (int q = 0; q < 4; q++) op[q] = elu1(acc[4 + q] * inv + bias[col0 + 4 + q]);
    *(float4*)&outf[(size_t)w * 256 + col0]     = o0;
    *(float4*)&outf[(size_t)w * 256 + col0 + 4] = o1;
}

// ---------------- final: out[g] = (pool2[g]/cnt[g]) @ fc2^T + b ----------------
__global__ void pool_fin2_k(const int* __restrict__ batch,
                            const float* __restrict__ fc2t,
                            const float* __restrict__ fcb2,
                            float* __restrict__ out)
{
    __shared__ float v[256];
    __shared__ float sinv;
    int g = blockIdx.x, t = threadIdx.x;
    if (t == 0) {
        int a = 0, b = NN;
        while (a < b) { int m = (a + b) >> 1; if (batch[m] < g) a = m + 1; else b = m; }
        int lo = a;
        a = lo; b = NN;
        while (a < b) { int m = (a + b) >> 1; if (batch[m] < g + 1) a = m + 1; else b = m; }
        sinv = 1.0f / fmaxf((float)(a - lo), 1.0f);
    }
    __syncthreads();
    v[t] = g_pool2[g * 256 + t] * sinv;
    __syncthreads();
    if (t < 32) {
        float s = fcb2[t];
        const float* wrow = fc2t + t * 256;
        #pragma unroll 8
        for (int k = 0; k < 256; k++) s = fmaf(v[k], wrow[k], s);
        out[g * 32 + t] = s;
    }
}

// ============================================================================
static void launch_gemm(const float* A, const float* bt, float* C,
                        int n, int K, int ncols, const float* bias, int act,
                        const float* att_s = nullptr, const float* att_d = nullptr,
                        float* as_o = nullptr, float* ad_o = nullptr,
                        float* pool_o = nullptr, const int* batchv = nullptr)
{
    dim3 grid((n + 127) / 128, (ncols + 127) / 128);
    mma_gemm_k<<<grid, 256, 2 * BUF32 * sizeof(uint32_t)>>>(
        A, bt, C, n, K, ncols, bias, act, att_s, att_d, as_o, ad_o, pool_o, batchv);
}

extern "C" void kernel_launch(void* const* d_in, const int* in_sizes, int n_in,
                              void* d_out, int out_size)
{
    const float* x     = (const float*)d_in[0];
    const int*   ei    = (const int*)  d_in[1];
    const float* ea    = (const float*)d_in[2];
    const int*   batch = (const int*)  d_in[3];
    const float* W1  = (const float*)d_in[4];
    const float* as1 = (const float*)d_in[5];
    const float* ad1 = (const float*)d_in[6];
    const float* We1 = (const float*)d_in[7];
    const float* ae1 = (const float*)d_in[8];
    const float* b1  = (const float*)d_in[9];
    const float* W2  = (const float*)d_in[10];
    const float* as2 = (const float*)d_in[11];
    const float* ad2 = (const float*)d_in[12];
    const float* We2 = (const float*)d_in[13];
    const float* ae2 = (const float*)d_in[14];
    const float* b2  = (const float*)d_in[15];
    const float* W3  = (const float*)d_in[16];
    const float* as3 = (const float*)d_in[17];
    const float* ad3 = (const float*)d_in[18];
    const float* We3 = (const float*)d_in[19];
    const float* ae3 = (const float*)d_in[20];
    const float* b3  = (const float*)d_in[21];
    const float* fcW1 = (const float*)d_in[22];
    const float* fcb1 = (const float*)d_in[23];
    const float* fcW2 = (const float*)d_in[24];
    const float* fcb2 = (const float*)d_in[25];

    const int* src = ei;
    const int* dst = ei + EE;

    float *feat, *h, *as_, *ad_, *btall, *pool2;
    cudaGetSymbolAddress((void**)&feat,  g_feat);
    cudaGetSymbolAddress((void**)&h,     g_h);
    cudaGetSymbolAddress((void**)&as_,   g_as);
    cudaGetSymbolAddress((void**)&ad_,   g_ad);
    cudaGetSymbolAddress((void**)&btall, g_btall);
    cudaGetSymbolAddress((void**)&pool2, g_pool2);

    cudaFuncSetAttribute(mma_gemm_k, cudaFuncAttributeMaxDynamicSharedMemorySize,
                         2 * BUF32 * sizeof(uint32_t));

    const int nb = (NN + 511) / 512;
    const int gb = (NN * 32 + 255) / 256;

    // launches 1-3
    transpose_all_k<<<dim3(8, 8, 5), dim3(32, 8)>>>(W1, W2, W3, fcW1, fcW2);   // 1
    ve_all_k<<<1, 96>>>(We1, ae1, We2, ae2, We3, ae3);                          // 2
    init_k<<<(NN + 255) / 256, 256>>>();                                        // 3

    // launch 4 = GEMM layer 1 (ncu capture lands here)
    launch_gemm(x, btall, h, NN, 128, HC, nullptr, 0, as1, ad1, as_, ad_);      // 4

    // CSR build (scan2 fused into scan3)
    hist_k<<<(EE + 255) / 256, 256>>>(dst);                                     // 5
    scan1_k<<<nb, 512>>>();                                                     // 6
    scan3_k<<<(NN + 255) / 256, 256>>>(nb);                                     // 7
    scatter_k<<<(EE + 255) / 256, 256>>>(src, dst, ea);                         // 8

    gat_edge_k<8><<<gb, 256>>>(as_, ad_, h, b1, feat, 0);                       // 9

    // layer 2
    launch_gemm(feat, btall + 1 * 65536, h, NN, 256, HC, nullptr, 0, as2, ad2, as_, ad_);
    gat_edge_k<8><<<gb, 256>>>(as_, ad_, h, b2, feat, 40);

    // layer 3 (H=1: 8 partial slots, summed in edge kernel)
    launch_gemm(feat, btall + 2 * 65536, h, NN, 256, HC, nullptr, 0, as3, ad3, as_, ad_);
    gat_edge_k<1><<<gb, 256>>>(as_, ad_, h, b3, feat, 80);

    // fc1 + gelu + pooling fused; then tiny (pool/cnt)@fc2 with bsearch counts
    launch_gemm(feat, btall + 3 * 65536, nullptr, NN, 256, 256, fcb1, 1,
                nullptr, nullptr, nullptr, nullptr, pool2, batch);
    pool_fin2_k<<<GG, 256>>>(batch, btall + 4 * 65536, fcb2, (float*)d_out);
}

// round 16
// speedup vs baseline: 1.1531x; 1.0382x over previous
#include <cuda_runtime.h>
#include <cuda_bf16.h>
#include <math.h>
#include <stdint.h>

#define NN 50000
#define EE 400000
#define GG 64
#define HC 256

// ---------------- scratch (static device globals) ---------------------------
__device__ float g_feat [NN * HC];
__device__ float g_h    [NN * HC];
__device__ float g_as   [NN * 8];
__device__ float g_ad   [NN * 8];
__device__ float g_VeAll[96];
__device__ float g_pool2[GG * 256];
__device__ float g_btall[5 * 256 * 256];
// CSR
__device__ int   g_deg [NN];
__device__ int   g_rs  [NN];
__device__ int   g_wp  [NN];
__device__ int   g_part[128];
__device__ int   g_csrc[EE];
__device__ float g_cea [EE * 5];

// ---------------- helpers ---------------------------------------------------
__device__ __forceinline__ float elu1(float x) { return x > 0.0f ? x : expm1f(x); }
__device__ __forceinline__ float gelu1(float x) {
    return 0.5f * x * (1.0f + erff(x * 0.70710678118654752f));
}

__device__ __forceinline__ uint32_t bfpack(float lo_e, float hi_e) {
    uint32_t r;
    asm("cvt.rn.bf16x2.f32 %0, %1, %2;" : "=r"(r) : "f"(hi_e), "f"(lo_e));
    return r;
}
__device__ __forceinline__ float bfround(float x) {
    uint16_t b;
    asm("cvt.rn.bf16.f32 %0, %1;" : "=h"(b) : "f"(x));
    float r;
    asm("cvt.f32.bf16 %0, %1;" : "=f"(r) : "h"(b));
    return r;
}

__device__ __forceinline__ void mma_bf16(float* d, const uint32_t* a,
                                         uint32_t b0, uint32_t b1) {
    asm volatile(
        "mma.sync.aligned.m16n8k16.row.col.f32.bf16.bf16.f32 "
        "{%0,%1,%2,%3}, {%4,%5,%6,%7}, {%8,%9}, {%0,%1,%2,%3};"
        : "+f"(d[0]), "+f"(d[1]), "+f"(d[2]), "+f"(d[3])
        : "r"(a[0]), "r"(a[1]), "r"(a[2]), "r"(a[3]), "r"(b0), "r"(b1));
}

#define LDSM4(r, addr) \
    asm volatile("ldmatrix.sync.aligned.m8n8.x4.shared.b16 {%0,%1,%2,%3}, [%4];" \
        : "=r"((r)[0]), "=r"((r)[1]), "=r"((r)[2]), "=r"((r)[3]) : "r"(addr))

// ---------------- warp-MMA 3xBF16 GEMM, 128x128 CTA tile ---------------------
#define S32 12
#define TILE32 (128 * S32)
#define BUF32 (4 * TILE32)

__global__ void __launch_bounds__(256, 2)
mma_gemm_k(const float* __restrict__ A, const float* __restrict__ Bt,
           float* __restrict__ C, int Nrows, int K, int ncols,
           const float* __restrict__ bias, int act,
           const float* __restrict__ att_s, const float* __restrict__ att_d,
           float* __restrict__ as_out, float* __restrict__ ad_out,
           float* __restrict__ pool_out, const int* __restrict__ batchv)
{
    extern __shared__ uint32_t sm32[];
    uint32_t sbase;
    asm("{ .reg .u64 t; cvta.to.shared.u64 t, %1; cvt.u32.u64 %0, t; }"
        : "=r"(sbase) : "l"(sm32));

    const int tid = threadIdx.x;
    const int lane = tid & 31, wid = tid >> 5;
    const int wr = wid >> 2, wc = wid & 3;
    const int tg = lane >> 2, tig = lane & 3;
    const int m0 = blockIdx.x * 128, n0 = blockIdx.y * 128;
    const int jcnt = max(0, min(4, (ncols - n0 - wc * 32 + 7) >> 3));

    const int lr = lane & 7, seg = lane >> 3;
    const uint32_t aoff = (uint32_t)((wr * 64 + lr + (seg & 1) * 8) * S32) * 4
                        + (uint32_t)(seg >> 1) * 16;
    const uint32_t boff = (uint32_t)((wc * 32 + (seg >> 1) * 8 + lr) * S32) * 4
                        + (uint32_t)(seg & 1) * 16;

    float acc[4][4][4];
    #pragma unroll
    for (int i = 0; i < 4; i++)
        #pragma unroll
        for (int j = 0; j < 4; j++)
            #pragma unroll
            for (int q = 0; q < 4; q++) acc[i][j][q] = 0.0f;

    const int nc = K / 16;
    // staging: each thread owns (row = tid>>1, half = tid&1) -> 8 contiguous vals
    const int lrow = tid >> 1, lhalf = tid & 1;
    float4 av0, av1, bv0, bv1;

    auto loadG = [&](int c) {
        const int k0 = c * 16 + lhalf * 8;
        const float4 z = make_float4(0.f, 0.f, 0.f, 0.f);
        int grow = m0 + lrow;
        if (grow < Nrows) {
            av0 = *(const float4*)&A[(size_t)grow * K + k0];
            av1 = *(const float4*)&A[(size_t)grow * K + k0 + 4];
        } else { av0 = z; av1 = z; }
        int gn = n0 + lrow;
        if (gn < ncols) {
            bv0 = *(const float4*)&Bt[(size_t)gn * K + k0];
            bv1 = *(const float4*)&Bt[(size_t)gn * K + k0 + 4];
        } else { bv0 = z; bv1 = z; }
    };
    auto storeS = [&](int buf) {
        uint32_t* base = sm32 + buf * BUF32;
        const int o = lrow * S32 + lhalf * 4;
        // A split -> 1 uint4 hi + 1 uint4 lo (STS.128)
        {
            float h0 = bfround(av0.x), h1 = bfround(av0.y);
            float h2 = bfround(av0.z), h3 = bfround(av0.w);
            float h4 = bfround(av1.x), h5 = bfround(av1.y);
            float h6 = bfround(av1.z), h7 = bfround(av1.w);
            uint4 hi = make_uint4(bfpack(h0, h1), bfpack(h2, h3),
                                  bfpack(h4, h5), bfpack(h6, h7));
            uint4 lo = make_uint4(bfpack(av0.x - h0, av0.y - h1),
                                  bfpack(av0.z - h2, av0.w - h3),
                                  bfpack(av1.x - h4, av1.y - h5),
                                  bfpack(av1.z - h6, av1.w - h7));
            *(uint4*)(base + o)          = hi;
            *(uint4*)(base + TILE32 + o) = lo;
        }
        // B split
        {
            float h0 = bfround(bv0.x), h1 = bfround(bv0.y);
            float h2 = bfround(bv0.z), h3 = bfround(bv0.w);
            float h4 = bfround(bv1.x), h5 = bfround(bv1.y);
            float h6 = bfround(bv1.z), h7 = bfround(bv1.w);
            uint4 hi = make_uint4(bfpack(h0, h1), bfpack(h2, h3),
                                  bfpack(h4, h5), bfpack(h6, h7));
            uint4 lo = make_uint4(bfpack(bv0.x - h0, bv0.y - h1),
                                  bfpack(bv0.z - h2, bv0.w - h3),
                                  bfpack(bv1.x - h4, bv1.y - h5),
                                  bfpack(bv1.z - h6, bv1.w - h7));
            *(uint4*)(base + 2 * TILE32 + o) = hi;
            *(uint4*)(base + 3 * TILE32 + o) = lo;
        }
    };
    auto compute = [&](int buf) {
        const uint32_t bb = sbase + (uint32_t)buf * BUF32 * 4;
        const uint32_t a_h = bb + aoff;
        const uint32_t a_l = a_h + TILE32 * 4;
        const uint32_t b_h = bb + 2 * TILE32 * 4 + boff;
        const uint32_t b_l = b_h + TILE32 * 4;

        uint32_t ah[4][4], al[4][4];
        #pragma unroll
        for (int i = 0; i < 4; i++) {
            LDSM4(ah[i], a_h + (uint32_t)(i * 16 * S32) * 4);
            LDSM4(al[i], a_l + (uint32_t)(i * 16 * S32) * 4);
        }
        #pragma unroll
        for (int jp = 0; jp < 2; jp++) {
            uint32_t th[4], tl[4];
            LDSM4(th, b_h + (uint32_t)(jp * 16 * S32) * 4);
            LDSM4(tl, b_l + (uint32_t)(jp * 16 * S32) * 4);
            #pragma unroll
            for (int jj = 0; jj < 2; jj++) {
                int j = jp * 2 + jj;
                if (j >= jcnt) break;
                #pragma unroll
                for (int i = 0; i < 4; i++) {
                    mma_bf16(acc[i][j], ah[i], th[jj * 2], th[jj * 2 + 1]);
                    mma_bf16(acc[i][j], ah[i], tl[jj * 2], tl[jj * 2 + 1]);
                    mma_bf16(acc[i][j], al[i], th[jj * 2], th[jj * 2 + 1]);
                }
            }
        }
    };

    loadG(0); storeS(0);
    __syncthreads();
    for (int c = 0; c < nc; c++) {
        if (c + 1 < nc) loadG(c + 1);
        compute(c & 1);
        if (c + 1 < nc) storeS((c + 1) & 1);
        __syncthreads();
    }

    // ---- C store epilogue ----
    if (C) {
        #pragma unroll
        for (int i = 0; i < 4; i++) {
            int row = m0 + wr * 64 + i * 16 + tg;
            #pragma unroll
            for (int j = 0; j < 4; j++) {
                int col = n0 + wc * 32 + j * 8 + tig * 2;
                if (col >= ncols) continue;
                #pragma unroll
                for (int half = 0; half < 2; half++) {
                    int r = row + half * 8;
                    if (r >= Nrows) continue;
                    float v0 = acc[i][j][half * 2 + 0];
                    float v1 = acc[i][j][half * 2 + 1];
                    if (bias) { v0 += bias[col]; v1 += bias[col + 1]; }
                    if (act == 1) { v0 = gelu1(v0); v1 = gelu1(v1); }
                    *(float2*)&C[(size_t)r * ncols + col] = make_float2(v0, v1);
                }
            }
        }
    }

    // ---- fused node-attention dots (plain stores, 8-slot layout) ----
    if (as_out) {
        const int slot = (n0 >> 5) + wc;
        #pragma unroll
        for (int i = 0; i < 4; i++) {
            float s1 = 0.f, d1 = 0.f, s2 = 0.f, d2 = 0.f;
            #pragma unroll
            for (int j = 0; j < 4; j++) {
                int col = n0 + wc * 32 + j * 8 + tig * 2;
                float a0 = att_s[col], a1 = att_s[col + 1];
                float b0 = att_d[col], b1 = att_d[col + 1];
                s1 += acc[i][j][0] * a0 + acc[i][j][1] * a1;
                d1 += acc[i][j][0] * b0 + acc[i][j][1] * b1;
                s2 += acc[i][j][2] * a0 + acc[i][j][3] * a1;
                d2 += acc[i][j][2] * b0 + acc[i][j][3] * b1;
            }
            s1 += __shfl_xor_sync(0xffffffffu, s1, 1); s1 += __shfl_xor_sync(0xffffffffu, s1, 2);
            d1 += __shfl_xor_sync(0xffffffffu, d1, 1); d1 += __shfl_xor_sync(0xffffffffu, d1, 2);
            s2 += __shfl_xor_sync(0xffffffffu, s2, 1); s2 += __shfl_xor_sync(0xffffffffu, s2, 2);
            d2 += __shfl_xor_sync(0xffffffffu, d2, 1); d2 += __shfl_xor_sync(0xffffffffu, d2, 2);
            if (tig == 0) {
                int r1 = m0 + wr * 64 + i * 16 + tg;
                int r2 = r1 + 8;
                if (r1 < Nrows) { as_out[r1 * 8 + slot] = s1; ad_out[r1 * 8 + slot] = d1; }
                if (r2 < Nrows) { as_out[r2 * 8 + slot] = s2; ad_out[r2 * 8 + slot] = d2; }
            }
        }
    }

    // ---- fused gelu + segment-sum pooling (fc1 + pool) ----
    if (pool_out) {
        const int rbase = m0 + wr * 64;
        bool uniform = (rbase + 63 < Nrows) && (batchv[rbase] == batchv[rbase + 63]);
        if (uniform) {
            int g = batchv[rbase];
            #pragma unroll
            for (int j = 0; j < 4; j++) {
                #pragma unroll
                for (int qc = 0; qc < 2; qc++) {
                    int col = n0 + wc * 32 + j * 8 + tig * 2 + qc;
                    float sum = 0.f;
                    #pragma unroll
                    for (int i = 0; i < 4; i++)
                        #pragma unroll
                        for (int half = 0; half < 2; half++)
                            sum += gelu1(acc[i][j][half * 2 + qc] + bias[col]);
                    atomicAdd(&pool_out[g * 256 + col], sum);
                }
            }
        } else {
            #pragma unroll
            for (int i = 0; i < 4; i++)
                #pragma unroll
                for (int j = 0; j < 4; j++)
                    #pragma unroll
                    for (int q = 0; q < 4; q++) {
                        int r = rbase + i * 16 + tg + (q >> 1) * 8;
                        if (r >= Nrows) continue;
                        int col = n0 + wc * 32 + j * 8 + tig * 2 + (q & 1);
                        float v = gelu1(acc[i][j][q] + bias[col]);
                        atomicAdd(&pool_out[batchv[r] * 256 + col], v);
                    }
        }
    }
}

// ---------------- batched weight transpose (all 5 at once) -------------------
__global__ void transpose_all_k(const float* __restrict__ W1, const float* __restrict__ W2,
                                const float* __restrict__ W3, const float* __restrict__ f1,
                                const float* __restrict__ f2)
{
    __shared__ float t[32][33];
    int z = blockIdx.z;
    const float* W = (z == 0) ? W1 : (z == 1) ? W2 : (z == 2) ? W3 : (z == 3) ? f1 : f2;
    int K = (z == 0) ? 128 : 256;
    int M = (z == 4) ? 32 : 256;
    float* Bt = g_btall + z * 65536;
    int m0 = blockIdx.x * 32, k0 = blockIdx.y * 32;
    if (m0 >= M || k0 >= K) return;
    for (int i = threadIdx.y; i < 32; i += 8) {
        int k = k0 + i, m = m0 + threadIdx.x;
        t[i][threadIdx.x] = (k < K && m < M) ? W[(size_t)k * M + m] : 0.f;
    }
    __syncthreads();
    for (int i = threadIdx.y; i < 32; i += 8) {
        int m = m0 + i, k = k0 + threadIdx.x;
        if (m < M && k < K) Bt[(size_t)m * K + k] = t[threadIdx.x][i];
    }
}

// ---------------- batched Ve ---------------------------------------------------
__global__ void ve_all_k(const float* __restrict__ We1, const float* __restrict__ ae1,
                         const float* __restrict__ We2, const float* __restrict__ ae2,
                         const float* __restrict__ We3, const float* __restrict__ ae3)
{
    int tid = threadIdx.x;
    const float* We; const float* ae; int H, base, loc;
    if (tid < 40)      { We = We1; ae = ae1; H = 8; base = 0;  loc = tid; }
    else if (tid < 80) { We = We2; ae = ae2; H = 8; base = 40; loc = tid - 40; }
    else if (tid < 85) { We = We3; ae = ae3; H = 1; base = 80; loc = tid - 80; }
    else return;
    int d = loc / H, h = loc % H;
    int C = 256 / H;
    float s = 0.0f;
    for (int c = 0; c < C; c++) s += We[d * 256 + h * C + c] * ae[h * C + c];
    g_VeAll[base + loc] = s;
}

// ---------------- init ----------------------------------------------------------
__global__ void init_k()
{
    int i = blockIdx.x * blockDim.x + threadIdx.x;
    if (i < NN) g_deg[i] = 0;
    if (i < GG * 256) g_pool2[i] = 0.0f;
}

// ---------------- CSR build ------------------------------------------------------
__global__ void hist_k(const int* __restrict__ dst)
{
    int e = blockIdx.x * blockDim.x + threadIdx.x;
    if (e < EE) atomicAdd(&g_deg[dst[e]], 1);
}
__global__ void scan1_k()
{
    __shared__ int s[512];
    int tid = threadIdx.x;
    int i = blockIdx.x * 512 + tid;
    int v = (i < NN) ? g_deg[i] : 0;
    s[tid] = v;
    __syncthreads();
    for (int off = 1; off < 512; off <<= 1) {
        int t = (tid >= off) ? s[tid - off] : 0;
        __syncthreads();
        s[tid] += t;
        __syncthreads();
    }
    if (i < NN) g_rs[i] = s[tid] - v;
    if (tid == 511) g_part[blockIdx.x] = s[511];
}
// scan3 with fused scan2: each CTA sums the block-partials it needs directly.
__global__ void scan3_k(int nb)
{
    __shared__ int sprefix;
    int i = blockIdx.x * blockDim.x + threadIdx.x;
    if (threadIdx.x == 0) {
        int myblk = (blockIdx.x * blockDim.x) >> 9;
        int s = 0;
        for (int k = 0; k < myblk; k++) s += g_part[k];
        sprefix = s;
    }
    __syncthreads();
    if (i >= NN) return;
    int blk = i >> 9;
    int mybase = (blockIdx.x * blockDim.x) >> 9;
    int pre = sprefix;
    if (blk != mybase) pre += g_part[blk - 1];
    int r = g_rs[i] + pre;
    g_rs[i] = r;
    g_wp[i] = r;
}
__global__ void scatter_k(const int* __restrict__ src, const int* __restrict__ dst,
                          const float* __restrict__ ea)
{
    int e = blockIdx.x * blockDim.x + threadIdx.x;
    if (e >= EE) return;
    int d = dst[e];
    int pos = atomicAdd(&g_wp[d], 1);
    g_csrc[pos] = src[e];
    #pragma unroll
    for (int i = 0; i < 5; i++) g_cea[(size_t)pos * 5 + i] = ea[(size_t)e * 5 + i];
}

// ---------------- fused single-pass edge softmax + aggregation ---------------
template <int H>
__global__ void __launch_bounds__(256)
gat_edge_k(const float* __restrict__ as_, const float* __restrict__ ad_,
           const float* __restrict__ hfeat, const float* __restrict__ bias,
           float* __restrict__ outf, int veBase)
{
    int w = (blockIdx.x * blockDim.x + threadIdx.x) >> 5;
    if (w >= NN) return;
    int lane = threadIdx.x & 31;
    const int head = (H == 8) ? (lane >> 2) : 0;
    const int tig = lane & 3;
    const int col0 = lane * 8;

    float ve[5];
    #pragma unroll
    for (int i = 0; i < 5; i++) ve[i] = g_VeAll[veBase + i * H + head];

    float adv;
    if (H == 1) {
        float4 a0 = *(const float4*)&ad_[w * 8];
        float4 a1 = *(const float4*)&ad_[w * 8 + 4];
        adv = a0.x + a0.y + a0.z + a0.w + a1.x + a1.y + a1.z + a1.w;
    } else {
        adv = ad_[w * 8 + head];
    }
    const int r0 = g_rs[w], dg = g_deg[w];

    float den = 0.0f;
    float acc[8];
    #pragma unroll
    for (int q = 0; q < 8; q++) acc[q] = 0.0f;

    for (int j = 0; j < dg; j += 4) {
        int jj = j + tig;
        bool valid = jj < dg;
        int je = r0 + (valid ? jj : 0);
        int sq = g_csrc[je];
        const float* ce = g_cea + (size_t)je * 5;
        float asv;
        if (H == 1) {
            float4 a0 = *(const float4*)&as_[sq * 8];
            float4 a1 = *(const float4*)&as_[sq * 8 + 4];
            asv = a0.x + a0.y + a0.z + a0.w + a1.x + a1.y + a1.z + a1.w;
        } else {
            asv = as_[sq * 8 + head];
        }
        float a = asv + adv;
        #pragma unroll
        for (int i = 0; i < 5; i++) a = fmaf(ce[i], ve[i], a);
        a = a > 0.0f ? a : 0.2f * a;
        float pq = valid ? __expf(a) : 0.0f;
        #pragma unroll
        for (int q = 0; q < 4; q++) {
            float p = __shfl_sync(0xffffffffu, pq, (lane & ~3) | q);
            int s   = __shfl_sync(0xffffffffu, sq, q);
            if (p != 0.0f) {
                den += p;
                const float4* hp = (const float4*)(hfeat + (size_t)s * 256 + col0);
                float4 v0 = hp[0], v1 = hp[1];
                acc[0] = fmaf(p, v0.x, acc[0]); acc[1] = fmaf(p, v0.y, acc[1]);
                acc[2] = fmaf(p, v0.z, acc[2]); acc[3] = fmaf(p, v0.w, acc[3]);
                acc[4] = fmaf(p, v1.x, acc[4]); acc[5] = fmaf(p, v1.y, acc[5]);
                acc[6] = fmaf(p, v1.z, acc[6]); acc[7] = fmaf(p, v1.w, acc[7]);
            }
        }
    }

    float inv = 1.0f / (den + 1e-16f);
    float4 o0, o1;
    float* op = (float*)&o0;
    #pragma unroll
    for (int q = 0; q < 4; q++) op[q] = elu1(acc[q] * inv + bias[col0 + q]);
    op = (float*)&o1;
    #pragma unroll
    for (int q = 0; q < 4; q++) op[q] = elu1(acc[4 + q] * inv + bias[col0 + 4 + q]);
    *(float4*)&outf[(size_t)w * 256 + col0]     = o0;
    *(float4*)&outf[(size_t)w * 256 + col0 + 4] = o1;
}

// ---------------- final: out[g] = (pool2[g]/cnt[g]) @ fc2^T + b ----------------
__global__ void pool_fin2_k(const int* __restrict__ batch,
                            const float* __restrict__ fc2t,
                            const float* __restrict__ fcb2,
                            float* __restrict__ out)
{
    __shared__ float v[256];
    __shared__ float sinv;
    int g = blockIdx.x, t = threadIdx.x;
    if (t == 0) {
        int a = 0, b = NN;
        while (a < b) { int m = (a + b) >> 1; if (batch[m] < g) a = m + 1; else b = m; }
        int lo = a;
        a = lo; b = NN;
        while (a < b) { int m = (a + b) >> 1; if (batch[m] < g + 1) a = m + 1; else b = m; }
        sinv = 1.0f / fmaxf((float)(a - lo), 1.0f);
    }
    __syncthreads();
    v[t] = g_pool2[g * 256 + t] * sinv;
    __syncthreads();
    if (t < 32) {
        float s = fcb2[t];
        const float* wrow = fc2t + t * 256;
        #pragma unroll 8
        for (int k = 0; k < 256; k++) s = fmaf(v[k], wrow[k], s);
        out[g * 32 + t] = s;
    }
}

// ============================================================================
static void launch_gemm(const float* A, const float* bt, float* C,
                        int n, int K, int ncols, const float* bias, int act,
                        const float* att_s = nullptr, const float* att_d = nullptr,
                        float* as_o = nullptr, float* ad_o = nullptr,
                        float* pool_o = nullptr, const int* batchv = nullptr)
{
    dim3 grid((n + 127) / 128, (ncols + 127) / 128);
    mma_gemm_k<<<grid, 256, 2 * BUF32 * sizeof(uint32_t)>>>(
        A, bt, C, n, K, ncols, bias, act, att_s, att_d, as_o, ad_o, pool_o, batchv);
}

extern "C" void kernel_launch(void* const* d_in, const int* in_sizes, int n_in,
                              void* d_out, int out_size)
{
    const float* x     = (const float*)d_in[0];
    const int*   ei    = (const int*)  d_in[1];
    const float* ea    = (const float*)d_in[2];
    const int*   batch = (const int*)  d_in[3];
    const float* W1  = (const float*)d_in[4];
    const float* as1 = (const float*)d_in[5];
    const float* ad1 = (const float*)d_in[6];
    const float* We1 = (const float*)d_in[7];
    const float* ae1 = (const float*)d_in[8];
    const float* b1  = (const float*)d_in[9];
    const float* W2  = (const float*)d_in[10];
    const float* as2 = (const float*)d_in[11];
    const float* ad2 = (const float*)d_in[12];
    const float* We2 = (const float*)d_in[13];
    const float* ae2 = (const float*)d_in[14];
    const float* b2  = (const float*)d_in[15];
    const float* W3  = (const float*)d_in[16];
    const float* as3 = (const float*)d_in[17];
    const float* ad3 = (const float*)d_in[18];
    const float* We3 = (const float*)d_in[19];
    const float* ae3 = (const float*)d_in[20];
    const float* b3  = (const float*)d_in[21];
    const float* fcW1 = (const float*)d_in[22];
    const float* fcb1 = (const float*)d_in[23];
    const float* fcW2 = (const float*)d_in[24];
    const float* fcb2 = (const float*)d_in[25];

    const int* src = ei;
    const int* dst = ei + EE;

    float *feat, *h, *as_, *ad_, *btall, *pool2;
    cudaGetSymbolAddress((void**)&feat,  g_feat);
    cudaGetSymbolAddress((void**)&h,     g_h);
    cudaGetSymbolAddress((void**)&as_,   g_as);
    cudaGetSymbolAddress((void**)&ad_,   g_ad);
    cudaGetSymbolAddress((void**)&btall, g_btall);
    cudaGetSymbolAddress((void**)&pool2, g_pool2);

    cudaFuncSetAttribute(mma_gemm_k, cudaFuncAttributeMaxDynamicSharedMemorySize,
                         2 * BUF32 * sizeof(uint32_t));

    const int nb = (NN + 511) / 512;
    const int gb = (NN * 32 + 255) / 256;

    // launches 1-3
    transpose_all_k<<<dim3(8, 8, 5), dim3(32, 8)>>>(W1, W2, W3, fcW1, fcW2);   // 1
    ve_all_k<<<1, 96>>>(We1, ae1, We2, ae2, We3, ae3);                          // 2
    init_k<<<(NN + 255) / 256, 256>>>();                                        // 3

    // launch 4 = GEMM layer 1 (ncu capture lands here)
    launch_gemm(x, btall, h, NN, 128, HC, nullptr, 0, as1, ad1, as_, ad_);      // 4

    // CSR build
    hist_k<<<(EE + 255) / 256, 256>>>(dst);                                     // 5
    scan1_k<<<nb, 512>>>();                                                     // 6
    scan3_k<<<(NN + 255) / 256, 256>>>(nb);                                     // 7
    scatter_k<<<(EE + 255) / 256, 256>>>(src, dst, ea);                         // 8

    gat_edge_k<8><<<gb, 256>>>(as_, ad_, h, b1, feat, 0);                       // 9

    // layer 2
    launch_gemm(feat, btall + 1 * 65536, h, NN, 256, HC, nullptr, 0, as2, ad2, as_, ad_);
    gat_edge_k<8><<<gb, 256>>>(as_, ad_, h, b2, feat, 40);

    // layer 3 (H=1: 8 partial slots, summed in edge kernel)
    launch_gemm(feat, btall + 2 * 65536, h, NN, 256, HC, nullptr, 0, as3, ad3, as_, ad_);
    gat_edge_k<1><<<gb, 256>>>(as_, ad_, h, b3, feat, 80);

    // fc1 + gelu + pooling fused; then tiny (pool/cnt)@fc2 with bsearch counts
    launch_gemm(feat, btall + 3 * 65536, nullptr, NN, 256, 256, fcb1, 1,
                nullptr, nullptr, nullptr, nullptr, pool2, batch);
    pool_fin2_k<<<GG, 256>>>(batch, btall + 4 * 65536, fcb2, (float*)d_out);
}

// round 17
// speedup vs baseline: 1.1711x; 1.0156x over previous
#include <cuda_runtime.h>
#include <cuda_bf16.h>
#include <math.h>
#include <stdint.h>

#define NN 50000
#define EE 400000
#define GG 64
#define HC 256

// ---------------- scratch (static device globals) ---------------------------
__device__ float g_feat [NN * HC];
__device__ float g_h    [NN * HC];
__device__ float g_as   [NN * 8];
__device__ float g_ad   [NN * 8];
__device__ float g_VeAll[96];
__device__ float g_pool2[GG * 256];
__device__ float g_btall[5 * 256 * 256];
// CSR
__device__ int   g_deg [NN];
__device__ int   g_rs  [NN];
__device__ int   g_wp  [NN];
__device__ int   g_part[128];
__device__ int   g_csrc[EE];
__device__ float g_cea [EE * 8];     // padded to 8 floats/edge (2x float4)

// ---------------- helpers ---------------------------------------------------
__device__ __forceinline__ float elu1(float x) { return x > 0.0f ? x : expm1f(x); }
__device__ __forceinline__ float gelu1(float x) {
    return 0.5f * x * (1.0f + erff(x * 0.70710678118654752f));
}

__device__ __forceinline__ uint32_t bfpack(float lo_e, float hi_e) {
    uint32_t r;
    asm("cvt.rn.bf16x2.f32 %0, %1, %2;" : "=r"(r) : "f"(hi_e), "f"(lo_e));
    return r;
}
__device__ __forceinline__ float bfround(float x) {
    uint16_t b;
    asm("cvt.rn.bf16.f32 %0, %1;" : "=h"(b) : "f"(x));
    float r;
    asm("cvt.f32.bf16 %0, %1;" : "=f"(r) : "h"(b));
    return r;
}

__device__ __forceinline__ void mma_bf16(float* d, const uint32_t* a,
                                         uint32_t b0, uint32_t b1) {
    asm volatile(
        "mma.sync.aligned.m16n8k16.row.col.f32.bf16.bf16.f32 "
        "{%0,%1,%2,%3}, {%4,%5,%6,%7}, {%8,%9}, {%0,%1,%2,%3};"
        : "+f"(d[0]), "+f"(d[1]), "+f"(d[2]), "+f"(d[3])
        : "r"(a[0]), "r"(a[1]), "r"(a[2]), "r"(a[3]), "r"(b0), "r"(b1));
}

#define LDSM4(r, addr) \
    asm volatile("ldmatrix.sync.aligned.m8n8.x4.shared.b16 {%0,%1,%2,%3}, [%4];" \
        : "=r"((r)[0]), "=r"((r)[1]), "=r"((r)[2]), "=r"((r)[3]) : "r"(addr))

// ---------------- warp-MMA 3xBF16 GEMM, 128x128 CTA tile ---------------------
#define S32 12
#define TILE32 (128 * S32)
#define BUF32 (4 * TILE32)

__global__ void __launch_bounds__(256, 2)
mma_gemm_k(const float* __restrict__ A, const float* __restrict__ Bt,
           float* __restrict__ C, int Nrows, int K, int ncols,
           const float* __restrict__ bias, int act,
           const float* __restrict__ att_s, const float* __restrict__ att_d,
           float* __restrict__ as_out, float* __restrict__ ad_out,
           float* __restrict__ pool_out, const int* __restrict__ batchv)
{
    extern __shared__ uint32_t sm32[];
    uint32_t sbase;
    asm("{ .reg .u64 t; cvta.to.shared.u64 t, %1; cvt.u32.u64 %0, t; }"
        : "=r"(sbase) : "l"(sm32));

    const int tid = threadIdx.x;
    const int lane = tid & 31, wid = tid >> 5;
    const int wr = wid >> 2, wc = wid & 3;
    const int tg = lane >> 2, tig = lane & 3;
    const int m0 = blockIdx.x * 128, n0 = blockIdx.y * 128;
    const int jcnt = max(0, min(4, (ncols - n0 - wc * 32 + 7) >> 3));

    const int lr = lane & 7, seg = lane >> 3;
    const uint32_t aoff = (uint32_t)((wr * 64 + lr + (seg & 1) * 8) * S32) * 4
                        + (uint32_t)(seg >> 1) * 16;
    const uint32_t boff = (uint32_t)((wc * 32 + (seg >> 1) * 8 + lr) * S32) * 4
                        + (uint32_t)(seg & 1) * 16;

    float acc[4][4][4];
    #pragma unroll
    for (int i = 0; i < 4; i++)
        #pragma unroll
        for (int j = 0; j < 4; j++)
            #pragma unroll
            for (int q = 0; q < 4; q++) acc[i][j][q] = 0.0f;

    const int nc = K / 16;
    const int lrow = tid >> 1, lhalf = tid & 1;
    float4 av0, av1, bv0, bv1;

    auto loadG = [&](int c) {
        const int k0 = c * 16 + lhalf * 8;
        const float4 z = make_float4(0.f, 0.f, 0.f, 0.f);
        int grow = m0 + lrow;
        if (grow < Nrows) {
            av0 = *(const float4*)&A[(size_t)grow * K + k0];
            av1 = *(const float4*)&A[(size_t)grow * K + k0 + 4];
        } else { av0 = z; av1 = z; }
        int gn = n0 + lrow;
        if (gn < ncols) {
            bv0 = *(const float4*)&Bt[(size_t)gn * K + k0];
            bv1 = *(const float4*)&Bt[(size_t)gn * K + k0 + 4];
        } else { bv0 = z; bv1 = z; }
    };
    auto storeS = [&](int buf) {
        uint32_t* base = sm32 + buf * BUF32;
        const int o = lrow * S32 + lhalf * 4;
        {
            float h0 = bfround(av0.x), h1 = bfround(av0.y);
            float h2 = bfround(av0.z), h3 = bfround(av0.w);
            float h4 = bfround(av1.x), h5 = bfround(av1.y);
            float h6 = bfround(av1.z), h7 = bfround(av1.w);
            uint4 hi = make_uint4(bfpack(h0, h1), bfpack(h2, h3),
                                  bfpack(h4, h5), bfpack(h6, h7));
            uint4 lo = make_uint4(bfpack(av0.x - h0, av0.y - h1),
                                  bfpack(av0.z - h2, av0.w - h3),
                                  bfpack(av1.x - h4, av1.y - h5),
                                  bfpack(av1.z - h6, av1.w - h7));
            *(uint4*)(base + o)          = hi;
            *(uint4*)(base + TILE32 + o) = lo;
        }
        {
            float h0 = bfround(bv0.x), h1 = bfround(bv0.y);
            float h2 = bfround(bv0.z), h3 = bfround(bv0.w);
            float h4 = bfround(bv1.x), h5 = bfround(bv1.y);
            float h6 = bfround(bv1.z), h7 = bfround(bv1.w);
            uint4 hi = make_uint4(bfpack(h0, h1), bfpack(h2, h3),
                                  bfpack(h4, h5), bfpack(h6, h7));
            uint4 lo = make_uint4(bfpack(bv0.x - h0, bv0.y - h1),
                                  bfpack(bv0.z - h2, bv0.w - h3),
                                  bfpack(bv1.x - h4, bv1.y - h5),
                                  bfpack(bv1.z - h6, bv1.w - h7));
            *(uint4*)(base + 2 * TILE32 + o) = hi;
            *(uint4*)(base + 3 * TILE32 + o) = lo;
        }
    };
    auto compute = [&](int buf) {
        const uint32_t bb = sbase + (uint32_t)buf * BUF32 * 4;
        const uint32_t a_h = bb + aoff;
        const uint32_t a_l = a_h + TILE32 * 4;
        const uint32_t b_h = bb + 2 * TILE32 * 4 + boff;
        const uint32_t b_l = b_h + TILE32 * 4;

        uint32_t ah[4][4], al[4][4];
        #pragma unroll
        for (int i = 0; i < 4; i++) {
            LDSM4(ah[i], a_h + (uint32_t)(i * 16 * S32) * 4);
            LDSM4(al[i], a_l + (uint32_t)(i * 16 * S32) * 4);
        }
        #pragma unroll
        for (int jp = 0; jp < 2; jp++) {
            uint32_t th[4], tl[4];
            LDSM4(th, b_h + (uint32_t)(jp * 16 * S32) * 4);
            LDSM4(tl, b_l + (uint32_t)(jp * 16 * S32) * 4);
            #pragma unroll
            for (int jj = 0; jj < 2; jj++) {
                int j = jp * 2 + jj;
                if (j >= jcnt) break;
                #pragma unroll
                for (int i = 0; i < 4; i++) {
                    mma_bf16(acc[i][j], ah[i], th[jj * 2], th[jj * 2 + 1]);
                    mma_bf16(acc[i][j], ah[i], tl[jj * 2], tl[jj * 2 + 1]);
                    mma_bf16(acc[i][j], al[i], th[jj * 2], th[jj * 2 + 1]);
                }
            }
        }
    };

    loadG(0); storeS(0);
    __syncthreads();
    for (int c = 0; c < nc; c++) {
        if (c + 1 < nc) loadG(c + 1);
        compute(c & 1);
        if (c + 1 < nc) storeS((c + 1) & 1);
        __syncthreads();
    }

    // ---- C store epilogue ----
    if (C) {
        #pragma unroll
        for (int i = 0; i < 4; i++) {
            int row = m0 + wr * 64 + i * 16 + tg;
            #pragma unroll
            for (int j = 0; j < 4; j++) {
                int col = n0 + wc * 32 + j * 8 + tig * 2;
                if (col >= ncols) continue;
                #pragma unroll
                for (int half = 0; half < 2; half++) {
                    int r = row + half * 8;
                    if (r >= Nrows) continue;
                    float v0 = acc[i][j][half * 2 + 0];
                    float v1 = acc[i][j][half * 2 + 1];
                    if (bias) { v0 += bias[col]; v1 += bias[col + 1]; }
                    if (act == 1) { v0 = gelu1(v0); v1 = gelu1(v1); }
                    *(float2*)&C[(size_t)r * ncols + col] = make_float2(v0, v1);
                }
            }
        }
    }

    // ---- fused node-attention dots (plain stores, 8-slot layout) ----
    if (as_out) {
        const int slot = (n0 >> 5) + wc;
        #pragma unroll
        for (int i = 0; i < 4; i++) {
            float s1 = 0.f, d1 = 0.f, s2 = 0.f, d2 = 0.f;
            #pragma unroll
            for (int j = 0; j < 4; j++) {
                int col = n0 + wc * 32 + j * 8 + tig * 2;
                float a0 = att_s[col], a1 = att_s[col + 1];
                float b0 = att_d[col], b1 = att_d[col + 1];
                s1 += acc[i][j][0] * a0 + acc[i][j][1] * a1;
                d1 += acc[i][j][0] * b0 + acc[i][j][1] * b1;
                s2 += acc[i][j][2] * a0 + acc[i][j][3] * a1;
                d2 += acc[i][j][2] * b0 + acc[i][j][3] * b1;
            }
            s1 += __shfl_xor_sync(0xffffffffu, s1, 1); s1 += __shfl_xor_sync(0xffffffffu, s1, 2);
            d1 += __shfl_xor_sync(0xffffffffu, d1, 1); d1 += __shfl_xor_sync(0xffffffffu, d1, 2);
            s2 += __shfl_xor_sync(0xffffffffu, s2, 1); s2 += __shfl_xor_sync(0xffffffffu, s2, 2);
            d2 += __shfl_xor_sync(0xffffffffu, d2, 1); d2 += __shfl_xor_sync(0xffffffffu, d2, 2);
            if (tig == 0) {
                int r1 = m0 + wr * 64 + i * 16 + tg;
                int r2 = r1 + 8;
                if (r1 < Nrows) { as_out[r1 * 8 + slot] = s1; ad_out[r1 * 8 + slot] = d1; }
                if (r2 < Nrows) { as_out[r2 * 8 + slot] = s2; ad_out[r2 * 8 + slot] = d2; }
            }
        }
    }

    // ---- fused gelu + segment-sum pooling (fc1 + pool) ----
    if (pool_out) {
        const int rbase = m0 + wr * 64;
        bool uniform = (rbase + 63 < Nrows) && (batchv[rbase] == batchv[rbase + 63]);
        if (uniform) {
            int g = batchv[rbase];
            #pragma unroll
            for (int j = 0; j < 4; j++) {
                #pragma unroll
                for (int qc = 0; qc < 2; qc++) {
                    int col = n0 + wc * 32 + j * 8 + tig * 2 + qc;
                    float sum = 0.f;
                    #pragma unroll
                    for (int i = 0; i < 4; i++)
                        #pragma unroll
                        for (int half = 0; half < 2; half++)
                            sum += gelu1(acc[i][j][half * 2 + qc] + bias[col]);
                    atomicAdd(&pool_out[g * 256 + col], sum);
                }
            }
        } else {
            #pragma unroll
            for (int i = 0; i < 4; i++)
                #pragma unroll
                for (int j = 0; j < 4; j++)
                    #pragma unroll
                    for (int q = 0; q < 4; q++) {
                        int r = rbase + i * 16 + tg + (q >> 1) * 8;
                        if (r >= Nrows) continue;
                        int col = n0 + wc * 32 + j * 8 + tig * 2 + (q & 1);
                        float v = gelu1(acc[i][j][q] + bias[col]);
                        atomicAdd(&pool_out[batchv[r] * 256 + col], v);
                    }
        }
    }
}

// ------- batched weight transpose + Ve projections (one kernel, z=0..5) ------
__global__ void transpose_all_k(const float* __restrict__ W1, const float* __restrict__ W2,
                                const float* __restrict__ W3, const float* __restrict__ f1,
                                const float* __restrict__ f2,
                                const float* __restrict__ We1, const float* __restrict__ ae1,
                                const float* __restrict__ We2, const float* __restrict__ ae2,
                                const float* __restrict__ We3, const float* __restrict__ ae3)
{
    int z = blockIdx.z;
    if (z == 5) {
        if (blockIdx.x != 0 || blockIdx.y != 0) return;
        int tid = threadIdx.y * 32 + threadIdx.x;
        const float* We; const float* ae; int H, base, loc;
        if (tid < 40)      { We = We1; ae = ae1; H = 8; base = 0;  loc = tid; }
        else if (tid < 80) { We = We2; ae = ae2; H = 8; base = 40; loc = tid - 40; }
        else if (tid < 85) { We = We3; ae = ae3; H = 1; base = 80; loc = tid - 80; }
        else return;
        int d = loc / H, h = loc % H;
        int C = 256 / H;
        float s = 0.0f;
        for (int c = 0; c < C; c++) s += We[d * 256 + h * C + c] * ae[h * C + c];
        g_VeAll[base + loc] = s;
        return;
    }
    __shared__ float t[32][33];
    const float* W = (z == 0) ? W1 : (z == 1) ? W2 : (z == 2) ? W3 : (z == 3) ? f1 : f2;
    int K = (z == 0) ? 128 : 256;
    int M = (z == 4) ? 32 : 256;
    float* Bt = g_btall + z * 65536;
    int m0 = blockIdx.x * 32, k0 = blockIdx.y * 32;
    if (m0 >= M || k0 >= K) return;
    for (int i = threadIdx.y; i < 32; i += 8) {
        int k = k0 + i, m = m0 + threadIdx.x;
        t[i][threadIdx.x] = (k < K && m < M) ? W[(size_t)k * M + m] : 0.f;
    }
    __syncthreads();
    for (int i = threadIdx.y; i < 32; i += 8) {
        int m = m0 + i, k = k0 + threadIdx.x;
        if (m < M && k < K) Bt[(size_t)m * K + k] = t[threadIdx.x][i];
    }
}

// ---------------- init ----------------------------------------------------------
__global__ void init_k()
{
    int i = blockIdx.x * blockDim.x + threadIdx.x;
    if (i < NN) g_deg[i] = 0;
    if (i < GG * 256) g_pool2[i] = 0.0f;
}

// ---------------- CSR build ------------------------------------------------------
__global__ void hist_k(const int* __restrict__ dst)
{
    int e = blockIdx.x * blockDim.x + threadIdx.x;
    if (e < EE) atomicAdd(&g_deg[dst[e]], 1);
}
__global__ void scan1_k()
{
    __shared__ int s[512];
    int tid = threadIdx.x;
    int i = blockIdx.x * 512 + tid;
    int v = (i < NN) ? g_deg[i] : 0;
    s[tid] = v;
    __syncthreads();
    for (int off = 1; off < 512; off <<= 1) {
        int t = (tid >= off) ? s[tid - off] : 0;
        __syncthreads();
        s[tid] += t;
        __syncthreads();
    }
    if (i < NN) g_rs[i] = s[tid] - v;
    if (tid == 511) g_part[blockIdx.x] = s[511];
}
__global__ void scan3_k(int nb)
{
    __shared__ int sprefix;
    int i = blockIdx.x * blockDim.x + threadIdx.x;
    if (threadIdx.x == 0) {
        int myblk = (blockIdx.x * blockDim.x) >> 9;
        int s = 0;
        for (int k = 0; k < myblk; k++) s += g_part[k];
        sprefix = s;
    }
    __syncthreads();
    if (i >= NN) return;
    int blk = i >> 9;
    int mybase = (blockIdx.x * blockDim.x) >> 9;
    int pre = sprefix;
    if (blk != mybase) pre += g_part[blk - 1];
    int r = g_rs[i] + pre;
    g_rs[i] = r;
    g_wp[i] = r;
}
__global__ void scatter_k(const int* __restrict__ src, const int* __restrict__ dst,
                          const float* __restrict__ ea)
{
    int e = blockIdx.x * blockDim.x + threadIdx.x;
    if (e >= EE) return;
    int d = dst[e];
    int pos = atomicAdd(&g_wp[d], 1);
    g_csrc[pos] = src[e];
    const float* ep = ea + (size_t)e * 5;
    float4 c0 = make_float4(ep[0], ep[1], ep[2], ep[3]);
    float4 c1 = make_float4(ep[4], 0.f, 0.f, 0.f);
    *(float4*)&g_cea[(size_t)pos * 8]     = c0;
    *(float4*)&g_cea[(size_t)pos * 8 + 4] = c1;
}

// ---------------- fused single-pass edge softmax + aggregation ---------------
template <int H>
__global__ void __launch_bounds__(256)
gat_edge_k(const float* __restrict__ as_, const float* __restrict__ ad_,
           const float* __restrict__ hfeat, const float* __restrict__ bias,
           float* __restrict__ outf, int veBase)
{
    int w = (blockIdx.x * blockDim.x + threadIdx.x) >> 5;
    if (w >= NN) return;
    int lane = threadIdx.x & 31;
    const int head = (H == 8) ? (lane >> 2) : 0;
    const int tig = lane & 3;
    const int col0 = lane * 8;

    float ve[5];
    #pragma unroll
    for (int i = 0; i < 5; i++) ve[i] = g_VeAll[veBase + i * H + head];

    float adv;
    if (H == 1) {
        float4 a0 = *(const float4*)&ad_[w * 8];
        float4 a1 = *(const float4*)&ad_[w * 8 + 4];
        adv = a0.x + a0.y + a0.z + a0.w + a1.x + a1.y + a1.z + a1.w;
    } else {
        adv = ad_[w * 8 + head];
    }
    const int r0 = g_rs[w], dg = g_deg[w];

    float den = 0.0f;
    float acc[8];
    #pragma unroll
    for (int q = 0; q < 8; q++) acc[q] = 0.0f;

    for (int j = 0; j < dg; j += 4) {
        int jj = j + tig;
        bool valid = jj < dg;
        int je = r0 + (valid ? jj : 0);
        int sq = g_csrc[je];
        float4 c0 = *(const float4*)&g_cea[(size_t)je * 8];
        float  c4 = g_cea[(size_t)je * 8 + 4];
        float asv;
        if (H == 1) {
            float4 a0 = *(const float4*)&as_[sq * 8];
            float4 a1 = *(const float4*)&as_[sq * 8 + 4];
            asv = a0.x + a0.y + a0.z + a0.w + a1.x + a1.y + a1.z + a1.w;
        } else {
            asv = as_[sq * 8 + head];
        }
        float a = asv + adv;
        a = fmaf(c0.x, ve[0], a);
        a = fmaf(c0.y, ve[1], a);
        a = fmaf(c0.z, ve[2], a);
        a = fmaf(c0.w, ve[3], a);
        a = fmaf(c4,   ve[4], a);
        a = a > 0.0f ? a : 0.2f * a;
        float pq = valid ? __expf(a) : 0.0f;
        #pragma unroll
        for (int q = 0; q < 4; q++) {
            float p = __shfl_sync(0xffffffffu, pq, (lane & ~3) | q);
            int s   = __shfl_sync(0xffffffffu, sq, q);
            if (p != 0.0f) {
                den += p;
                const float4* hp = (const float4*)(hfeat + (size_t)s * 256 + col0);
                float4 v0 = hp[0], v1 = hp[1];
                acc[0] = fmaf(p, v0.x, acc[0]); acc[1] = fmaf(p, v0.y, acc[1]);
                acc[2] = fmaf(p, v0.z, acc[2]); acc[3] = fmaf(p, v0.w, acc[3]);
                acc[4] = fmaf(p, v1.x, acc[4]); acc[5] = fmaf(p, v1.y, acc[5]);
                acc[6] = fmaf(p, v1.z, acc[6]); acc[7] = fmaf(p, v1.w, acc[7]);
            }
        }
    }

    float inv = 1.0f / (den + 1e-16f);
    float4 o0, o1;
    float* op = (float*)&o0;
    #pragma unroll
    for (int q = 0; q < 4; q++) op[q] = elu1(acc[q] * inv + bias[col0 + q]);
    op = (float*)&o1;
    #pragma unroll
    for (int q = 0; q < 4; q++) op[q] = elu1(acc[4 + q] * inv + bias[col0 + 4 + q]);
    *(float4*)&outf[(size_t)w * 256 + col0]     = o0;
    *(float4*)&outf[(size_t)w * 256 + col0 + 4] = o1;
}

// ---------------- final: out[g] = (pool2[g]/cnt[g]) @ fc2^T + b ----------------
__global__ void pool_fin2_k(const int* __restrict__ batch,
                            const float* __restrict__ fc2t,
                            const float* __restrict__ fcb2,
                            float* __restrict__ out)
{
    __shared__ float v[256];
    __shared__ float sinv;
    int g = blockIdx.x, t = threadIdx.x;
    if (t == 0) {
        int a = 0, b = NN;
        while (a < b) { int m = (a + b) >> 1; if (batch[m] < g) a = m + 1; else b = m; }
        int lo = a;
        a = lo; b = NN;
        while (a < b) { int m = (a + b) >> 1; if (batch[m] < g + 1) a = m + 1; else b = m; }
        sinv = 1.0f / fmaxf((float)(a - lo), 1.0f);
    }
    __syncthreads();
    v[t] = g_pool2[g * 256 + t] * sinv;
    __syncthreads();
    if (t < 32) {
        float s = fcb2[t];
        const float* wrow = fc2t + t * 256;
        #pragma unroll 8
        for (int k = 0; k < 256; k++) s = fmaf(v[k], wrow[k], s);
        out[g * 32 + t] = s;
    }
}

// ============================================================================
static void launch_gemm(const float* A, const float* bt, float* C,
                        int n, int K, int ncols, const float* bias, int act,
                        const float* att_s = nullptr, const float* att_d = nullptr,
                        float* as_o = nullptr, float* ad_o = nullptr,
                        float* pool_o = nullptr, const int* batchv = nullptr)
{
    dim3 grid((n + 127) / 128, (ncols + 127) / 128);
    mma_gemm_k<<<grid, 256, 2 * BUF32 * sizeof(uint32_t)>>>(
        A, bt, C, n, K, ncols, bias, act, att_s, att_d, as_o, ad_o, pool_o, batchv);
}

extern "C" void kernel_launch(void* const* d_in, const int* in_sizes, int n_in,
                              void* d_out, int out_size)
{
    const float* x     = (const float*)d_in[0];
    const int*   ei    = (const int*)  d_in[1];
    const float* ea    = (const float*)d_in[2];
    const int*   batch = (const int*)  d_in[3];
    const float* W1  = (const float*)d_in[4];
    const float* as1 = (const float*)d_in[5];
    const float* ad1 = (const float*)d_in[6];
    const float* We1 = (const float*)d_in[7];
    const float* ae1 = (const float*)d_in[8];
    const float* b1  = (const float*)d_in[9];
    const float* W2  = (const float*)d_in[10];
    const float* as2 = (const float*)d_in[11];
    const float* ad2 = (const float*)d_in[12];
    const float* We2 = (const float*)d_in[13];
    const float* ae2 = (const float*)d_in[14];
    const float* b2  = (const float*)d_in[15];
    const float* W3  = (const float*)d_in[16];
    const float* as3 = (const float*)d_in[17];
    const float* ad3 = (const float*)d_in[18];
    const float* We3 = (const float*)d_in[19];
    const float* ae3 = (const float*)d_in[20];
    const float* b3  = (const float*)d_in[21];
    const float* fcW1 = (const float*)d_in[22];
    const float* fcb1 = (const float*)d_in[23];
    const float* fcW2 = (const float*)d_in[24];
    const float* fcb2 = (const float*)d_in[25];

    const int* src = ei;
    const int* dst = ei + EE;

    float *feat, *h, *as_, *ad_, *btall, *pool2;
    cudaGetSymbolAddress((void**)&feat,  g_feat);
    cudaGetSymbolAddress((void**)&h,     g_h);
    cudaGetSymbolAddress((void**)&as_,   g_as);
    cudaGetSymbolAddress((void**)&ad_,   g_ad);
    cudaGetSymbolAddress((void**)&btall, g_btall);
    cudaGetSymbolAddress((void**)&pool2, g_pool2);

    cudaFuncSetAttribute(mma_gemm_k, cudaFuncAttributeMaxDynamicSharedMemorySize,
                         2 * BUF32 * sizeof(uint32_t));

    const int nb = (NN + 511) / 512;
    const int gb = (NN * 32 + 255) / 256;

    // launches 1-3
    transpose_all_k<<<dim3(8, 8, 6), dim3(32, 8)>>>(W1, W2, W3, fcW1, fcW2,
                                                    We1, ae1, We2, ae2, We3, ae3); // 1
    init_k<<<(NN + 255) / 256, 256>>>();                                           // 2
    hist_k<<<(EE + 255) / 256, 256>>>(dst);                                        // 3

    // launch 4 = GEMM layer 1 (ncu capture lands here)
    launch_gemm(x, btall, h, NN, 128, HC, nullptr, 0, as1, ad1, as_, ad_);         // 4

    // CSR tail
    scan1_k<<<nb, 512>>>();                                                        // 5
    scan3_k<<<(NN + 255) / 256, 256>>>(nb);                                        // 6
    scatter_k<<<(EE + 255) / 256, 256>>>(src, dst, ea);                            // 7

    gat_edge_k<8><<<gb, 256>>>(as_, ad_, h, b1, feat, 0);                          // 8

    // layer 2
    launch_gemm(feat, btall + 1 * 65536, h, NN, 256, HC, nullptr, 0, as2, ad2, as_, ad_);
    gat_edge_k<8><<<gb, 256>>>(as_, ad_, h, b2, feat, 40);

    // layer 3 (H=1: 8 partial slots, summed in edge kernel)
    launch_gemm(feat, btall + 2 * 65536, h, NN, 256, HC, nullptr, 0, as3, ad3, as_, ad_);
    gat_edge_k<1><<<gb, 256>>>(as_, ad_, h, b3, feat, 80);

    // fc1 + gelu + pooling fused; then tiny (pool/cnt)@fc2 with bsearch counts
    launch_gemm(feat, btall + 3 * 65536, nullptr, NN, 256, 256, fcb1, 1,
                nullptr, nullptr, nullptr, nullptr, pool2, batch);
    pool_fin2_k<<<GG, 256>>>(batch, btall + 4 * 65536, fcb2, (float*)d_out);
}